// round 1
// baseline (speedup 1.0000x reference)
#include <cuda_runtime.h>

// Problem constants
constexpr int NB  = 256;     // batch
constexpr int NG  = 20000;   // genes
constexpr int NL  = 512;     // latent
constexpr int ND  = 256;     // gene embedding dim
constexpr int NH  = 8;       // heads
constexpr int NHD = 64;      // head dim
constexpr float ATT_SCALE = 0.125f;  // 64^-0.5
constexpr int KSPLIT = 25;
constexpr int KCH = NG / KSPLIT;     // 800, multiple of 16

// Scratch (static device globals; no allocation allowed)
__device__ float g_K[NG * NL];                     // 41 MB
__device__ float g_V[NG * NL];                     // 41 MB
__device__ float g_Q[NB * NL];
__device__ float g_ctx[NB * NL];
__device__ float g_h1[NB * NL];
__device__ float g_m[NB * NH];
__device__ float g_l[NB * NH];                     // stores 1/sumexp
__device__ float g_part[NH * KSPLIT * NB * NHD];   // 13 MB PV partials

// ---------------------------------------------------------------------------
// Generic tiled SGEMM, NT form: C[m,n] = alpha * sum_k A[m,k]*B[n,k] (+bias[n])
// Block tile 128x128, K-tile 16, 256 threads, 8x8 per-thread microtile.
// Batched over blockIdx.z with element strides. Requires K % 16 == 0,
// lda/ldb % 4 == 0, 16B-aligned base pointers.
// ---------------------------------------------------------------------------
__global__ __launch_bounds__(256) void sgemm_nt(
    const float* __restrict__ A, const float* __restrict__ Bm,
    float* __restrict__ C, const float* __restrict__ bias,
    int M, int N, int K, int lda, int ldb, long long ldc,
    long long sAz, long long sBz, long long sCz, float alpha)
{
    A  += (size_t)blockIdx.z * sAz;
    Bm += (size_t)blockIdx.z * sBz;
    C  += (size_t)blockIdx.z * sCz;

    __shared__ float As[16][128];
    __shared__ float Bs[16][128];

    const int tid   = threadIdx.x;
    const int mBase = blockIdx.x * 128;
    const int nBase = blockIdx.y * 128;
    const int tm = (tid >> 4) * 8;   // 0..120
    const int tn = (tid & 15) * 8;   // 0..120

    float acc[8][8] = {};

    for (int k0 = 0; k0 < K; k0 += 16) {
        // Load A tile (128 rows x 16 k) as 512 float4s, 2 per thread
        #pragma unroll
        for (int s = 0; s < 2; s++) {
            int f   = tid + s * 256;
            int row = f >> 2, kq = f & 3;
            int gm  = mBase + row;
            float4 v = make_float4(0.f, 0.f, 0.f, 0.f);
            if (gm < M)
                v = *reinterpret_cast<const float4*>(A + (size_t)gm * lda + k0 + kq * 4);
            As[kq * 4 + 0][row] = v.x; As[kq * 4 + 1][row] = v.y;
            As[kq * 4 + 2][row] = v.z; As[kq * 4 + 3][row] = v.w;
        }
        // Load B tile (128 rows x 16 k)
        #pragma unroll
        for (int s = 0; s < 2; s++) {
            int f   = tid + s * 256;
            int row = f >> 2, kq = f & 3;
            int gn  = nBase + row;
            float4 v = make_float4(0.f, 0.f, 0.f, 0.f);
            if (gn < N)
                v = *reinterpret_cast<const float4*>(Bm + (size_t)gn * ldb + k0 + kq * 4);
            Bs[kq * 4 + 0][row] = v.x; Bs[kq * 4 + 1][row] = v.y;
            Bs[kq * 4 + 2][row] = v.z; Bs[kq * 4 + 3][row] = v.w;
        }
        __syncthreads();

        #pragma unroll
        for (int kk = 0; kk < 16; kk++) {
            float a[8], b[8];
            #pragma unroll
            for (int i = 0; i < 8; i++) a[i] = As[kk][tm + i];
            #pragma unroll
            for (int j = 0; j < 8; j++) b[j] = Bs[kk][tn + j];
            #pragma unroll
            for (int i = 0; i < 8; i++)
                #pragma unroll
                for (int j = 0; j < 8; j++)
                    acc[i][j] += a[i] * b[j];
        }
        __syncthreads();
    }

    #pragma unroll
    for (int i = 0; i < 8; i++) {
        int gm = mBase + tm + i;
        if (gm < M) {
            #pragma unroll
            for (int j = 0; j < 8; j++) {
                int gn = nBase + tn + j;
                if (gn < N) {
                    float v = alpha * acc[i][j];
                    if (bias) v += bias[gn];
                    C[(size_t)gm * ldc + gn] = v;
                }
            }
        }
    }
}

// ---------------------------------------------------------------------------
// Per-(b,h) row softmax stats over G: online max + sumexp. Stores m and 1/l.
// One block per row, 256 threads.
// ---------------------------------------------------------------------------
__global__ __launch_bounds__(256) void softmax_stats_kernel(const float* __restrict__ S)
{
    const int row = blockIdx.x;                 // 0..NB*NH-1
    const float* s = S + (size_t)row * NG;
    const int tid = threadIdx.x;

    float m = -1e30f, l = 0.f;
    for (int i = tid; i < NG; i += 256) {
        float x = s[i];
        float mn = fmaxf(m, x);
        l = l * __expf(m - mn) + __expf(x - mn);
        m = mn;
    }
    __shared__ float sm[256], sl[256];
    sm[tid] = m; sl[tid] = l;
    __syncthreads();
    for (int off = 128; off; off >>= 1) {
        if (tid < off) {
            float m2 = sm[tid + off], l2 = sl[tid + off];
            float mn = fmaxf(sm[tid], m2);
            sl[tid] = sl[tid] * __expf(sm[tid] - mn) + l2 * __expf(m2 - mn);
            sm[tid] = mn;
        }
        __syncthreads();
    }
    if (tid == 0) {
        g_m[row] = sm[0];
        g_l[row] = 1.f / sl[0];
    }
}

// ---------------------------------------------------------------------------
// In-place normalize: S <- exp(S - m) / l.  Grid: (ceil(G/4/256), NB*NH)
// ---------------------------------------------------------------------------
__global__ __launch_bounds__(256) void softmax_norm_kernel(float* __restrict__ S)
{
    const int row = blockIdx.y;
    const float m    = g_m[row];
    const float invl = g_l[row];
    const int i4 = blockIdx.x * 256 + threadIdx.x;   // float4 index
    if (i4 < NG / 4) {
        float4* p = reinterpret_cast<float4*>(S + (size_t)row * NG) + i4;
        float4 v = *p;
        v.x = __expf(v.x - m) * invl;
        v.y = __expf(v.y - m) * invl;
        v.z = __expf(v.z - m) * invl;
        v.w = __expf(v.w - m) * invl;
        *p = v;
    }
}

// ---------------------------------------------------------------------------
// PV: partial[h,ks][b][d] = sum_{g in chunk ks} P[b,h,g] * V[g, h*64+d]
// NN GEMM tile 128x64, K-tile 16, 128 threads, 8x8 microtile.
// Grid: (NB/128, 1, NH*KSPLIT)
// ---------------------------------------------------------------------------
__global__ __launch_bounds__(128) void pv_kernel(
    const float* __restrict__ P, const float* __restrict__ Vv, float* __restrict__ part)
{
    const int h  = blockIdx.z / KSPLIT;
    const int ks = blockIdx.z % KSPLIT;
    const int tid = threadIdx.x;
    const int mBase = blockIdx.x * 128;

    const float* A  = P  + (size_t)h * NG;   // A[b][g] at A[b*NH*NG + g]
    const float* Bv = Vv + h * NHD;          // B[g][d] at Bv[g*NL + d]

    __shared__ float As[16][128];
    __shared__ float Bs[16][64];

    const int tm = (tid >> 3) * 8;  // 0..120
    const int tn = (tid & 7) * 8;   // 0..56
    float acc[8][8] = {};

    const int k0beg = ks * KCH;
    for (int k0 = k0beg; k0 < k0beg + KCH; k0 += 16) {
        // A tile 128x16 = 512 float4s, 4 per thread (M=256 exact, no guard)
        #pragma unroll
        for (int s = 0; s < 4; s++) {
            int f = tid + s * 128;
            int row = f >> 2, kq = f & 3;
            float4 v = *reinterpret_cast<const float4*>(
                A + (size_t)(mBase + row) * (NH * NG) + k0 + kq * 4);
            As[kq * 4 + 0][row] = v.x; As[kq * 4 + 1][row] = v.y;
            As[kq * 4 + 2][row] = v.z; As[kq * 4 + 3][row] = v.w;
        }
        // B tile 16x64 = 256 float4s, 2 per thread
        #pragma unroll
        for (int s = 0; s < 2; s++) {
            int f = tid + s * 128;
            int kr = f >> 4, dq = f & 15;
            float4 v = *reinterpret_cast<const float4*>(
                Bv + (size_t)(k0 + kr) * NL + dq * 4);
            *reinterpret_cast<float4*>(&Bs[kr][dq * 4]) = v;
        }
        __syncthreads();
        #pragma unroll
        for (int kk = 0; kk < 16; kk++) {
            float a[8], b[8];
            #pragma unroll
            for (int i = 0; i < 8; i++) a[i] = As[kk][tm + i];
            #pragma unroll
            for (int j = 0; j < 8; j++) b[j] = Bs[kk][tn + j];
            #pragma unroll
            for (int i = 0; i < 8; i++)
                #pragma unroll
                for (int j = 0; j < 8; j++)
                    acc[i][j] += a[i] * b[j];
        }
        __syncthreads();
    }

    float* Cp = part + ((size_t)blockIdx.z * NB + mBase) * NHD;
    #pragma unroll
    for (int i = 0; i < 8; i++)
        #pragma unroll
        for (int j = 0; j < 8; j++)
            Cp[(size_t)(tm + i) * NHD + tn + j] = acc[i][j];
}

// ---------------------------------------------------------------------------
// Reduce PV partials over KSPLIT: ctx[b][h*64+d] (deterministic order)
// ---------------------------------------------------------------------------
__global__ __launch_bounds__(256) void pv_reduce_kernel(
    const float* __restrict__ part, float* __restrict__ ctx)
{
    const int idx = blockIdx.x * 256 + threadIdx.x;   // < NB*NL
    const int b = idx >> 9;
    const int c = idx & 511;
    const int h = c >> 6;
    const int d = c & 63;
    float s = 0.f;
    #pragma unroll
    for (int ks = 0; ks < KSPLIT; ks++)
        s += part[(((size_t)(h * KSPLIT + ks)) * NB + b) * NHD + d];
    ctx[idx] = s;
}

// ---------------------------------------------------------------------------
// LayerNorm + ReLU in place on g_h1 rows of 512. One block per batch row.
// ---------------------------------------------------------------------------
__global__ __launch_bounds__(256) void ln_relu_kernel(
    float* __restrict__ hbuf, const float* __restrict__ g, const float* __restrict__ bt)
{
    const int b = blockIdx.x;
    const int tid = threadIdx.x;
    float* hrow = hbuf + (size_t)b * NL;
    float x0 = hrow[tid], x1 = hrow[tid + 256];

    __shared__ float s1[256], s2[256];
    s1[tid] = x0 + x1;
    s2[tid] = x0 * x0 + x1 * x1;
    __syncthreads();
    for (int off = 128; off; off >>= 1) {
        if (tid < off) { s1[tid] += s1[tid + off]; s2[tid] += s2[tid + off]; }
        __syncthreads();
    }
    const float mu  = s1[0] * (1.f / 512.f);
    const float var = s2[0] * (1.f / 512.f) - mu * mu;
    const float rs  = rsqrtf(var + 1e-5f);

    float y0 = (x0 - mu) * rs * g[tid]       + bt[tid];
    float y1 = (x1 - mu) * rs * g[tid + 256] + bt[tid + 256];
    hrow[tid]       = fmaxf(y0, 0.f);
    hrow[tid + 256] = fmaxf(y1, 0.f);
}

// ---------------------------------------------------------------------------
extern "C" void kernel_launch(void* const* d_in, const int* in_sizes, int n_in,
                              void* d_out, int out_size)
{
    const float* z   = (const float*)d_in[0];
    const float* E   = (const float*)d_in[1];
    const float* Wq  = (const float*)d_in[2];
    const float* bq  = (const float*)d_in[3];
    const float* Wk  = (const float*)d_in[4];
    const float* bk  = (const float*)d_in[5];
    const float* Wv  = (const float*)d_in[6];
    const float* bv  = (const float*)d_in[7];
    const float* W1  = (const float*)d_in[8];
    const float* b1  = (const float*)d_in[9];
    const float* lng = (const float*)d_in[10];
    const float* lnb = (const float*)d_in[11];
    const float* W2  = (const float*)d_in[12];
    const float* b2  = (const float*)d_in[13];

    float* out  = (float*)d_out;
    float* ga   = out;                          // gene_attention [NB, NG]
    float* attn = out + (size_t)NB * NG;        // attn [NB, NH, NG]

    float *pQ, *pK, *pV, *pCtx, *pH1, *pPart;
    cudaGetSymbolAddress((void**)&pQ,    g_Q);
    cudaGetSymbolAddress((void**)&pK,    g_K);
    cudaGetSymbolAddress((void**)&pV,    g_V);
    cudaGetSymbolAddress((void**)&pCtx,  g_ctx);
    cudaGetSymbolAddress((void**)&pH1,   g_h1);
    cudaGetSymbolAddress((void**)&pPart, g_part);

    const int gTiles = (NG + 127) / 128;   // 157

    // Q = z @ Wq^T + bq            [256,512]
    sgemm_nt<<<dim3(2, 4, 1), 256>>>(z, Wq, pQ, bq,
        NB, NL, NL, NL, NL, NL, 0, 0, 0, 1.f);
    // K = E @ Wk^T + bk            [20000,512]
    sgemm_nt<<<dim3(gTiles, 4, 1), 256>>>(E, Wk, pK, bk,
        NG, NL, ND, ND, ND, NL, 0, 0, 0, 1.f);
    // V = E @ Wv^T + bv            [20000,512]
    sgemm_nt<<<dim3(gTiles, 4, 1), 256>>>(E, Wv, pV, bv,
        NG, NL, ND, ND, ND, NL, 0, 0, 0, 1.f);
    // scores[b,h,g] = SCALE * Q[b,h,:]·K[g,h,:]  -> attn buffer (raw)
    sgemm_nt<<<dim3(2, gTiles, NH), 256>>>(pQ, pK, attn, nullptr,
        NB, NG, NHD, NL, NL, (long long)NH * NG,
        NHD, NHD, (long long)NG, ATT_SCALE);
    // softmax stats per (b,h) row
    softmax_stats_kernel<<<NB * NH, 256>>>(attn);
    // normalize in place -> attn output
    softmax_norm_kernel<<<dim3((NG / 4 + 255) / 256, NB * NH), 256>>>(attn);
    // ctx partials + reduce
    pv_kernel<<<dim3(2, 1, NH * KSPLIT), 128>>>(attn, pV, pPart);
    pv_reduce_kernel<<<(NB * NL) / 256, 256>>>(pPart, pCtx);
    // h1 = ctx @ W1^T + b1
    sgemm_nt<<<dim3(2, 4, 1), 256>>>(pCtx, W1, pH1, b1,
        NB, NL, NL, NL, NL, NL, 0, 0, 0, 1.f);
    // LayerNorm + ReLU in place
    ln_relu_kernel<<<NB, 256>>>(pH1, lng, lnb);
    // gene_attention = h1 @ W2^T + b2
    sgemm_nt<<<dim3(2, gTiles, 1), 256>>>(pH1, W2, ga, b2,
        NB, NG, NL, NL, NL, (long long)NG, 0, 0, 0, 1.f);
}

// round 4
// speedup vs baseline: 1.3464x; 1.3464x over previous
#include <cuda_runtime.h>

typedef unsigned long long ull;

// Problem constants
constexpr int NB  = 256;
constexpr int NG  = 20000;
constexpr int NL  = 512;
constexpr int ND  = 256;
constexpr int NH  = 8;
constexpr int NHD = 64;
constexpr float ATT_SCALE = 0.125f;
constexpr int KS = 9;            // PV k-split
constexpr int KCHUNK = 2224;     // 9*2224 >= 20000, all chunk lengths %16==0
constexpr int QSK = 4;           // split-K for the tiny 256x512x512 GEMMs

// Scratch (same footprint as the known-good R1 kernel; raw scores live in d_out)
__device__ float g_K[(size_t)NG * NL];
__device__ float g_V[(size_t)NG * NL];
__device__ float g_Q[NB * NL];
__device__ float g_ctx[NB * NL];
__device__ float g_h1[NB * NL];
__device__ float g_m[NB * NH];
__device__ float g_l[NB * NH];
__device__ float g_part[NH * KS * NB * NHD];
__device__ float g_qp[QSK * NB * NL];
__device__ float g_hp[QSK * NB * NL];

// ---- packed fp32x2 helpers (FFMA2: 2x the 3-reg FFMA rate on Blackwell) ----
__device__ __forceinline__ void fma2(ull& d, ull a, ull b) {
    asm("fma.rn.f32x2 %0, %1, %2, %0;" : "+l"(d) : "l"(a), "l"(b));
}
__device__ __forceinline__ ull pack2(float x) {
    ull r; unsigned u = __float_as_uint(x);
    asm("mov.b64 %0, {%1, %1};" : "=l"(r) : "r"(u));
    return r;
}
union F4 { float4 v; ull u[2]; float f[4]; };
union U2 { ull u; float2 f; };

__device__ __forceinline__ float4 expf4(float4 x, float m, float il) {
    x.x = __expf(x.x - m) * il; x.y = __expf(x.y - m) * il;
    x.z = __expf(x.z - m) * il; x.w = __expf(x.w - m) * il;
    return x;
}

// ---------------------------------------------------------------------------
// Tiled SGEMM NT: C[m,n] = alpha * sum_k A[m,k]*B[n,k] (+bias[n])
// 128x128 tile, Ktile 16, 256 threads, 8x8 microtile via fp32x2,
// double-buffered smem. z-dim batches via sAz/sBz/sCz (also used for split-K).
// ---------------------------------------------------------------------------
__global__ __launch_bounds__(256, 2) void sgemm_nt(
    const float* __restrict__ A, const float* __restrict__ Bm,
    float* __restrict__ C, const float* __restrict__ bias,
    int M, int N, int K, int lda, int ldb, long long ldc,
    long long sAz, long long sBz, long long sCz, float alpha)
{
    A  += (size_t)blockIdx.z * sAz;
    Bm += (size_t)blockIdx.z * sBz;
    C  += (size_t)blockIdx.z * sCz;

    __shared__ __align__(16) float As[2][16][128];
    __shared__ __align__(16) float Bs[2][16][128];

    const int tid   = threadIdx.x;
    const int mBase = blockIdx.x * 128;
    const int nBase = blockIdx.y * 128;
    const int tm = (tid >> 4) * 8;
    const int tn = (tid & 15) * 8;
    const int lrow = tid >> 2;          // 0..63 (+64 for s=1)
    const int lkq  = tid & 3;

    const float* aPtr[2]; const float* bPtr[2];
    bool aOk[2], bOk[2];
    #pragma unroll
    for (int s = 0; s < 2; s++) {
        int row = lrow + s * 64;
        int gm = mBase + row, gn = nBase + row;
        aOk[s] = gm < M; bOk[s] = gn < N;
        aPtr[s] = A  + (size_t)(aOk[s] ? gm : 0) * lda + lkq * 4;
        bPtr[s] = Bm + (size_t)(bOk[s] ? gn : 0) * ldb + lkq * 4;
    }

    ull acc[8][4];
    #pragma unroll
    for (int i = 0; i < 8; i++)
        #pragma unroll
        for (int j = 0; j < 4; j++) acc[i][j] = 0ull;

    F4 pa[2], pb[2];
    const float4 z4 = make_float4(0.f, 0.f, 0.f, 0.f);

    #pragma unroll
    for (int s = 0; s < 2; s++) {
        pa[s].v = aOk[s] ? *reinterpret_cast<const float4*>(aPtr[s]) : z4;
        pb[s].v = bOk[s] ? *reinterpret_cast<const float4*>(bPtr[s]) : z4;
        aPtr[s] += 16; bPtr[s] += 16;
    }
    #pragma unroll
    for (int s = 0; s < 2; s++) {
        int row = lrow + s * 64;
        #pragma unroll
        for (int c = 0; c < 4; c++) {
            As[0][lkq * 4 + c][row] = pa[s].f[c];
            Bs[0][lkq * 4 + c][row] = pb[s].f[c];
        }
    }
    __syncthreads();

    int buf = 0;
    const int nIter = K / 16;
    for (int it = 1; it < nIter; it++) {
        #pragma unroll
        for (int s = 0; s < 2; s++) {
            pa[s].v = aOk[s] ? *reinterpret_cast<const float4*>(aPtr[s]) : z4;
            pb[s].v = bOk[s] ? *reinterpret_cast<const float4*>(bPtr[s]) : z4;
            aPtr[s] += 16; bPtr[s] += 16;
        }
        #pragma unroll
        for (int kk = 0; kk < 16; kk++) {
            F4 a0, a1, b0, b1;
            a0.v = *reinterpret_cast<const float4*>(&As[buf][kk][tm]);
            a1.v = *reinterpret_cast<const float4*>(&As[buf][kk][tm + 4]);
            b0.v = *reinterpret_cast<const float4*>(&Bs[buf][kk][tn]);
            b1.v = *reinterpret_cast<const float4*>(&Bs[buf][kk][tn + 4]);
            #pragma unroll
            for (int i = 0; i < 8; i++) {
                ull aa = pack2(i < 4 ? a0.f[i] : a1.f[i - 4]);
                fma2(acc[i][0], aa, b0.u[0]);
                fma2(acc[i][1], aa, b0.u[1]);
                fma2(acc[i][2], aa, b1.u[0]);
                fma2(acc[i][3], aa, b1.u[1]);
            }
        }
        #pragma unroll
        for (int s = 0; s < 2; s++) {
            int row = lrow + s * 64;
            #pragma unroll
            for (int c = 0; c < 4; c++) {
                As[buf ^ 1][lkq * 4 + c][row] = pa[s].f[c];
                Bs[buf ^ 1][lkq * 4 + c][row] = pb[s].f[c];
            }
        }
        __syncthreads();
        buf ^= 1;
    }
    #pragma unroll
    for (int kk = 0; kk < 16; kk++) {
        F4 a0, a1, b0, b1;
        a0.v = *reinterpret_cast<const float4*>(&As[buf][kk][tm]);
        a1.v = *reinterpret_cast<const float4*>(&As[buf][kk][tm + 4]);
        b0.v = *reinterpret_cast<const float4*>(&Bs[buf][kk][tn]);
        b1.v = *reinterpret_cast<const float4*>(&Bs[buf][kk][tn + 4]);
        #pragma unroll
        for (int i = 0; i < 8; i++) {
            ull aa = pack2(i < 4 ? a0.f[i] : a1.f[i - 4]);
            fma2(acc[i][0], aa, b0.u[0]);
            fma2(acc[i][1], aa, b0.u[1]);
            fma2(acc[i][2], aa, b1.u[0]);
            fma2(acc[i][3], aa, b1.u[1]);
        }
    }

    #pragma unroll
    for (int i = 0; i < 8; i++) {
        int gm = mBase + tm + i;
        if (gm >= M) continue;
        #pragma unroll
        for (int jh = 0; jh < 2; jh++) {
            int gn = nBase + tn + jh * 4;
            if (gn >= N) continue;
            U2 p0, p1; p0.u = acc[i][jh * 2]; p1.u = acc[i][jh * 2 + 1];
            float4 v = make_float4(p0.f.x * alpha, p0.f.y * alpha,
                                   p1.f.x * alpha, p1.f.y * alpha);
            if (bias) {
                float4 bb = *reinterpret_cast<const float4*>(bias + gn);
                v.x += bb.x; v.y += bb.y; v.z += bb.z; v.w += bb.w;
            }
            *reinterpret_cast<float4*>(C + (size_t)gm * ldc + gn) = v;
        }
    }
}

// ---------------------------------------------------------------------------
// softmax row stats over G (reads raw scores); stores m and 1/sumexp
// ---------------------------------------------------------------------------
__global__ __launch_bounds__(256) void softmax_stats_kernel(const float* __restrict__ S)
{
    const int row = blockIdx.x;
    const float4* s4 = reinterpret_cast<const float4*>(S + (size_t)row * NG);
    const int tid = threadIdx.x;

    float m = -1e30f, l = 0.f;
    for (int i = tid; i < NG / 4; i += 256) {
        float4 x = s4[i];
        float mx = fmaxf(fmaxf(x.x, x.y), fmaxf(x.z, x.w));
        float mn = fmaxf(m, mx);
        l = l * __expf(m - mn) + __expf(x.x - mn) + __expf(x.y - mn)
                               + __expf(x.z - mn) + __expf(x.w - mn);
        m = mn;
    }
    __shared__ float sm[256], sl[256];
    sm[tid] = m; sl[tid] = l;
    __syncthreads();
    for (int off = 128; off; off >>= 1) {
        if (tid < off) {
            float m2 = sm[tid + off], l2 = sl[tid + off];
            float mn = fmaxf(sm[tid], m2);
            sl[tid] = sl[tid] * __expf(sm[tid] - mn) + l2 * __expf(m2 - mn);
            sm[tid] = mn;
        }
        __syncthreads();
    }
    if (tid == 0) { g_m[row] = sm[0]; g_l[row] = 1.f / sl[0]; }
}

// ---------------------------------------------------------------------------
// normalize raw scores IN PLACE (runs after PV has consumed the raw scores)
// ---------------------------------------------------------------------------
__global__ __launch_bounds__(256) void softmax_norm_kernel(float* __restrict__ S)
{
    const int row = blockIdx.y;
    const float m    = g_m[row];
    const float invl = g_l[row];
    const int i4 = blockIdx.x * 256 + threadIdx.x;
    if (i4 < NG / 4) {
        float4* p = reinterpret_cast<float4*>(S + (size_t)row * NG) + i4;
        *p = expf4(*p, m, invl);
    }
}

// ---------------------------------------------------------------------------
// PV with fused softmax: part[h,ks][b][d] = sum_g exp(S[b,h,g]-m)*invl * V[g,h*64+d]
// Reads RAW scores (S) + stats. 128(b) x 64(d) tile, 256 threads, 4x8 microtile.
// Grid: (2, 1, NH*KS)
// ---------------------------------------------------------------------------
__global__ __launch_bounds__(256, 2) void pv_kernel(
    const float* __restrict__ S, const float* __restrict__ V, float* __restrict__ part)
{
    const int h  = blockIdx.z / KS;
    const int ks = blockIdx.z % KS;
    const int tid = threadIdx.x;
    const int mBase = blockIdx.x * 128;
    const int kbeg = ks * KCHUNK;
    const int kend = min(kbeg + KCHUNK, NG);
    const int nIter = (kend - kbeg) / 16;

    __shared__ __align__(16) float As[2][16][128];
    __shared__ __align__(16) float Bs[2][16][64];

    const int tm = (tid >> 3) * 4;   // 0..124
    const int tn = (tid & 7) * 8;    // 0..56

    const int lrow = tid >> 2, lkq = tid & 3;
    const float* sPtr[2]; float mrow[2], lrowv[2];
    #pragma unroll
    for (int s = 0; s < 2; s++) {
        int b = mBase + lrow + s * 64;
        sPtr[s] = S + (size_t)b * (NH * NG) + (size_t)h * NG + kbeg + lkq * 4;
        mrow[s]  = g_m[b * NH + h];
        lrowv[s] = g_l[b * NH + h];
    }
    const int lkr = tid >> 4, ldq = tid & 15;
    const float* vPtr = V + (size_t)(kbeg + lkr) * NL + h * NHD + ldq * 4;

    ull acc[4][4];
    #pragma unroll
    for (int i = 0; i < 4; i++)
        #pragma unroll
        for (int j = 0; j < 4; j++) acc[i][j] = 0ull;

    F4 pa[2], pb;

    #pragma unroll
    for (int s = 0; s < 2; s++) {
        pa[s].v = expf4(*reinterpret_cast<const float4*>(sPtr[s]), mrow[s], lrowv[s]);
        sPtr[s] += 16;
    }
    pb.v = *reinterpret_cast<const float4*>(vPtr); vPtr += 16 * NL;
    #pragma unroll
    for (int s = 0; s < 2; s++) {
        int row = lrow + s * 64;
        #pragma unroll
        for (int c = 0; c < 4; c++) As[0][lkq * 4 + c][row] = pa[s].f[c];
    }
    *reinterpret_cast<float4*>(&Bs[0][lkr][ldq * 4]) = pb.v;
    __syncthreads();

    int buf = 0;
    for (int it = 1; it < nIter; it++) {
        #pragma unroll
        for (int s = 0; s < 2; s++) {
            pa[s].v = expf4(*reinterpret_cast<const float4*>(sPtr[s]), mrow[s], lrowv[s]);
            sPtr[s] += 16;
        }
        pb.v = *reinterpret_cast<const float4*>(vPtr); vPtr += 16 * NL;

        #pragma unroll
        for (int kk = 0; kk < 16; kk++) {
            F4 a0, b0, b1;
            a0.v = *reinterpret_cast<const float4*>(&As[buf][kk][tm]);
            b0.v = *reinterpret_cast<const float4*>(&Bs[buf][kk][tn]);
            b1.v = *reinterpret_cast<const float4*>(&Bs[buf][kk][tn + 4]);
            #pragma unroll
            for (int i = 0; i < 4; i++) {
                ull aa = pack2(a0.f[i]);
                fma2(acc[i][0], aa, b0.u[0]);
                fma2(acc[i][1], aa, b0.u[1]);
                fma2(acc[i][2], aa, b1.u[0]);
                fma2(acc[i][3], aa, b1.u[1]);
            }
        }
        #pragma unroll
        for (int s = 0; s < 2; s++) {
            int row = lrow + s * 64;
            #pragma unroll
            for (int c = 0; c < 4; c++) As[buf ^ 1][lkq * 4 + c][row] = pa[s].f[c];
        }
        *reinterpret_cast<float4*>(&Bs[buf ^ 1][lkr][ldq * 4]) = pb.v;
        __syncthreads();
        buf ^= 1;
    }
    #pragma unroll
    for (int kk = 0; kk < 16; kk++) {
        F4 a0, b0, b1;
        a0.v = *reinterpret_cast<const float4*>(&As[buf][kk][tm]);
        b0.v = *reinterpret_cast<const float4*>(&Bs[buf][kk][tn]);
        b1.v = *reinterpret_cast<const float4*>(&Bs[buf][kk][tn + 4]);
        #pragma unroll
        for (int i = 0; i < 4; i++) {
            ull aa = pack2(a0.f[i]);
            fma2(acc[i][0], aa, b0.u[0]);
            fma2(acc[i][1], aa, b0.u[1]);
            fma2(acc[i][2], aa, b1.u[0]);
            fma2(acc[i][3], aa, b1.u[1]);
        }
    }

    float* Cp = part + ((size_t)blockIdx.z * NB + mBase) * NHD;
    #pragma unroll
    for (int i = 0; i < 4; i++) {
        #pragma unroll
        for (int jh = 0; jh < 2; jh++) {
            U2 p0, p1; p0.u = acc[i][jh * 2]; p1.u = acc[i][jh * 2 + 1];
            float4 v = make_float4(p0.f.x, p0.f.y, p1.f.x, p1.f.y);
            *reinterpret_cast<float4*>(Cp + (size_t)(tm + i) * NHD + tn + jh * 4) = v;
        }
    }
}

// reduce PV partials (KS chunks) -> ctx
__global__ __launch_bounds__(256) void pv_reduce_kernel(
    const float* __restrict__ part, float* __restrict__ ctx)
{
    const int idx = blockIdx.x * 256 + threadIdx.x;
    const int b = idx >> 9, c = idx & 511;
    const int h = c >> 6, d = c & 63;
    float s = 0.f;
    #pragma unroll
    for (int ks = 0; ks < KS; ks++)
        s += part[(((size_t)(h * KS + ks)) * NB + b) * NHD + d];
    ctx[idx] = s;
}

// reduce Q split-K partials + bias
__global__ __launch_bounds__(256) void q_reduce_kernel(
    const float* __restrict__ qp, const float* __restrict__ bq, float* __restrict__ Q)
{
    const int idx = blockIdx.x * 256 + threadIdx.x;  // < NB*NL
    float s = bq[idx & (NL - 1)];
    #pragma unroll
    for (int z = 0; z < QSK; z++) s += qp[(size_t)z * NB * NL + idx];
    Q[idx] = s;
}

// h1 split-K reduce + bias + LayerNorm + ReLU -> g_h1
__global__ __launch_bounds__(256) void ln_relu_kernel(
    const float* __restrict__ hp, const float* __restrict__ b1,
    const float* __restrict__ g, const float* __restrict__ bt, float* __restrict__ hout)
{
    const int b = blockIdx.x;
    const int tid = threadIdx.x;
    float x0 = b1[tid], x1 = b1[tid + 256];
    #pragma unroll
    for (int z = 0; z < QSK; z++) {
        x0 += hp[(size_t)z * NB * NL + (size_t)b * NL + tid];
        x1 += hp[(size_t)z * NB * NL + (size_t)b * NL + tid + 256];
    }
    __shared__ float s1[256], s2[256];
    s1[tid] = x0 + x1;
    s2[tid] = x0 * x0 + x1 * x1;
    __syncthreads();
    for (int off = 128; off; off >>= 1) {
        if (tid < off) { s1[tid] += s1[tid + off]; s2[tid] += s2[tid + off]; }
        __syncthreads();
    }
    const float mu  = s1[0] * (1.f / 512.f);
    const float var = s2[0] * (1.f / 512.f) - mu * mu;
    const float rs  = rsqrtf(var + 1e-5f);
    float y0 = (x0 - mu) * rs * g[tid]       + bt[tid];
    float y1 = (x1 - mu) * rs * g[tid + 256] + bt[tid + 256];
    hout[(size_t)b * NL + tid]       = fmaxf(y0, 0.f);
    hout[(size_t)b * NL + tid + 256] = fmaxf(y1, 0.f);
}

// ---------------------------------------------------------------------------
extern "C" void kernel_launch(void* const* d_in, const int* in_sizes, int n_in,
                              void* d_out, int out_size)
{
    const float* z   = (const float*)d_in[0];
    const float* E   = (const float*)d_in[1];
    const float* Wq  = (const float*)d_in[2];
    const float* bq  = (const float*)d_in[3];
    const float* Wk  = (const float*)d_in[4];
    const float* bk  = (const float*)d_in[5];
    const float* Wv  = (const float*)d_in[6];
    const float* bv  = (const float*)d_in[7];
    const float* W1  = (const float*)d_in[8];
    const float* b1  = (const float*)d_in[9];
    const float* lng = (const float*)d_in[10];
    const float* lnb = (const float*)d_in[11];
    const float* W2  = (const float*)d_in[12];
    const float* b2  = (const float*)d_in[13];

    float* out  = (float*)d_out;
    float* ga   = out;                          // gene_attention [NB, NG]
    float* attn = out + (size_t)NB * NG;        // attn [NB, NH, NG] (raw scores first)

    float *pK, *pV, *pQ, *pCtx, *pH1, *pPart, *pQp, *pHp;
    cudaGetSymbolAddress((void**)&pK,    g_K);
    cudaGetSymbolAddress((void**)&pV,    g_V);
    cudaGetSymbolAddress((void**)&pQ,    g_Q);
    cudaGetSymbolAddress((void**)&pCtx,  g_ctx);
    cudaGetSymbolAddress((void**)&pH1,   g_h1);
    cudaGetSymbolAddress((void**)&pPart, g_part);
    cudaGetSymbolAddress((void**)&pQp,   g_qp);
    cudaGetSymbolAddress((void**)&pHp,   g_hp);

    const int gTiles = (NG + 127) / 128;   // 157

    // Q partial = z @ Wq^T (split-K over z-dim, 128 k per slice)
    sgemm_nt<<<dim3(2, 4, QSK), 256>>>(z, Wq, pQp, nullptr,
        NB, NL, NL / QSK, NL, NL, NL, 128, 128, (long long)NB * NL, 1.f);
    q_reduce_kernel<<<(NB * NL) / 256, 256>>>(pQp, bq, pQ);
    // K, V projections
    sgemm_nt<<<dim3(gTiles, 4, 1), 256>>>(E, Wk, pK, bk,
        NG, NL, ND, ND, ND, NL, 0, 0, 0, 1.f);
    sgemm_nt<<<dim3(gTiles, 4, 1), 256>>>(E, Wv, pV, bv,
        NG, NL, ND, ND, ND, NL, 0, 0, 0, 1.f);
    // raw scores -> attn region of d_out
    sgemm_nt<<<dim3(2, gTiles, NH), 256>>>(pQ, pK, attn, nullptr,
        NB, NG, NHD, NL, NL, (long long)NH * NG,
        NHD, NHD, (long long)NG, ATT_SCALE);
    // softmax stats over raw scores
    softmax_stats_kernel<<<NB * NH, 256>>>(attn);
    // PV consumes RAW scores with fused exp (stream-ordered before norm)
    pv_kernel<<<dim3(2, 1, NH * KS), 256>>>(attn, pV, pPart);
    pv_reduce_kernel<<<(NB * NL) / 256, 256>>>(pPart, pCtx);
    // now normalize attn in place (raw -> softmax output)
    softmax_norm_kernel<<<dim3((NG / 4 + 255) / 256, NB * NH), 256>>>(attn);
    // h1 partial = ctx @ W1^T (split-K), then fused reduce+LN+ReLU
    sgemm_nt<<<dim3(2, 4, QSK), 256>>>(pCtx, W1, pHp, nullptr,
        NB, NL, NL / QSK, NL, NL, NL, 128, 128, (long long)NB * NL, 1.f);
    ln_relu_kernel<<<NB, 256>>>(pHp, b1, lng, lnb, pH1);
    // gene_attention = h1 @ W2^T + b2
    sgemm_nt<<<dim3(2, gTiles, 1), 256>>>(pH1, W2, ga, b2,
        NB, NG, NL, NL, NL, (long long)NG, 0, 0, 0, 1.f);
}

// round 5
// speedup vs baseline: 1.3488x; 1.0018x over previous
#include <cuda_runtime.h>

typedef unsigned long long ull;

// Problem constants
constexpr int NB  = 256;
constexpr int NG  = 20000;
constexpr int NL  = 512;
constexpr int ND  = 256;
constexpr int NH  = 8;
constexpr int NHD = 64;
constexpr float ATT_SCALE = 0.125f;
constexpr int KS = 9;            // PV k-split
constexpr int KCHUNK = 2224;     // 9*2224 >= 20000, all chunk lengths %16==0
constexpr int QSK = 4;           // split-K for the tiny 256x512x512 GEMMs

// Scratch (same footprint as the known-good R1 kernel; raw scores live in d_out)
__device__ float g_K[(size_t)NG * NL];
__device__ float g_V[(size_t)NG * NL];
__device__ float g_Q[NB * NL];
__device__ float g_ctx[NB * NL];
__device__ float g_h1[NB * NL];
__device__ float g_m[NB * NH];
__device__ float g_l[NB * NH];
__device__ float g_part[NH * KS * NB * NHD];
__device__ float g_qp[QSK * NB * NL];
__device__ float g_hp[QSK * NB * NL];

// ---- packed fp32x2 helpers (FFMA2: 2x the 3-reg FFMA rate on Blackwell) ----
__device__ __forceinline__ void fma2(ull& d, ull a, ull b) {
    asm("fma.rn.f32x2 %0, %1, %2, %0;" : "+l"(d) : "l"(a), "l"(b));
}
__device__ __forceinline__ ull pack2(float x) {
    ull r; unsigned u = __float_as_uint(x);
    asm("mov.b64 %0, {%1, %1};" : "=l"(r) : "r"(u));
    return r;
}
union F4 { float4 v; ull u[2]; float f[4]; };
union U2 { ull u; float2 f; };

__device__ __forceinline__ float4 expf4(float4 x, float m, float il) {
    x.x = __expf(x.x - m) * il; x.y = __expf(x.y - m) * il;
    x.z = __expf(x.z - m) * il; x.w = __expf(x.w - m) * il;
    return x;
}

// ---------------------------------------------------------------------------
// Tiled SGEMM NT: C[m,n] = alpha * sum_k A[m,k]*B[n,k] (+bias[n])
// 128x128 tile, Ktile 16, 256 threads, 8x8 microtile via fp32x2,
// double-buffered smem. z-dim batches via sAz/sBz/sCz (also used for split-K).
// ---------------------------------------------------------------------------
__global__ __launch_bounds__(256, 2) void sgemm_nt(
    const float* __restrict__ A, const float* __restrict__ Bm,
    float* __restrict__ C, const float* __restrict__ bias,
    int M, int N, int K, int lda, int ldb, long long ldc,
    long long sAz, long long sBz, long long sCz, float alpha)
{
    A  += (size_t)blockIdx.z * sAz;
    Bm += (size_t)blockIdx.z * sBz;
    C  += (size_t)blockIdx.z * sCz;

    __shared__ __align__(16) float As[2][16][128];
    __shared__ __align__(16) float Bs[2][16][128];

    const int tid   = threadIdx.x;
    const int mBase = blockIdx.x * 128;
    const int nBase = blockIdx.y * 128;
    const int tm = (tid >> 4) * 8;
    const int tn = (tid & 15) * 8;
    const int lrow = tid >> 2;          // 0..63 (+64 for s=1)
    const int lkq  = tid & 3;

    const float* aPtr[2]; const float* bPtr[2];
    bool aOk[2], bOk[2];
    #pragma unroll
    for (int s = 0; s < 2; s++) {
        int row = lrow + s * 64;
        int gm = mBase + row, gn = nBase + row;
        aOk[s] = gm < M; bOk[s] = gn < N;
        aPtr[s] = A  + (size_t)(aOk[s] ? gm : 0) * lda + lkq * 4;
        bPtr[s] = Bm + (size_t)(bOk[s] ? gn : 0) * ldb + lkq * 4;
    }

    ull acc[8][4];
    #pragma unroll
    for (int i = 0; i < 8; i++)
        #pragma unroll
        for (int j = 0; j < 4; j++) acc[i][j] = 0ull;

    F4 pa[2], pb[2];
    const float4 z4 = make_float4(0.f, 0.f, 0.f, 0.f);

    #pragma unroll
    for (int s = 0; s < 2; s++) {
        pa[s].v = aOk[s] ? *reinterpret_cast<const float4*>(aPtr[s]) : z4;
        pb[s].v = bOk[s] ? *reinterpret_cast<const float4*>(bPtr[s]) : z4;
        aPtr[s] += 16; bPtr[s] += 16;
    }
    #pragma unroll
    for (int s = 0; s < 2; s++) {
        int row = lrow + s * 64;
        #pragma unroll
        for (int c = 0; c < 4; c++) {
            As[0][lkq * 4 + c][row] = pa[s].f[c];
            Bs[0][lkq * 4 + c][row] = pb[s].f[c];
        }
    }
    __syncthreads();

    int buf = 0;
    const int nIter = K / 16;
    for (int it = 1; it < nIter; it++) {
        #pragma unroll
        for (int s = 0; s < 2; s++) {
            pa[s].v = aOk[s] ? *reinterpret_cast<const float4*>(aPtr[s]) : z4;
            pb[s].v = bOk[s] ? *reinterpret_cast<const float4*>(bPtr[s]) : z4;
            aPtr[s] += 16; bPtr[s] += 16;
        }
        #pragma unroll
        for (int kk = 0; kk < 16; kk++) {
            F4 a0, a1, b0, b1;
            a0.v = *reinterpret_cast<const float4*>(&As[buf][kk][tm]);
            a1.v = *reinterpret_cast<const float4*>(&As[buf][kk][tm + 4]);
            b0.v = *reinterpret_cast<const float4*>(&Bs[buf][kk][tn]);
            b1.v = *reinterpret_cast<const float4*>(&Bs[buf][kk][tn + 4]);
            #pragma unroll
            for (int i = 0; i < 8; i++) {
                ull aa = pack2(i < 4 ? a0.f[i] : a1.f[i - 4]);
                fma2(acc[i][0], aa, b0.u[0]);
                fma2(acc[i][1], aa, b0.u[1]);
                fma2(acc[i][2], aa, b1.u[0]);
                fma2(acc[i][3], aa, b1.u[1]);
            }
        }
        #pragma unroll
        for (int s = 0; s < 2; s++) {
            int row = lrow + s * 64;
            #pragma unroll
            for (int c = 0; c < 4; c++) {
                As[buf ^ 1][lkq * 4 + c][row] = pa[s].f[c];
                Bs[buf ^ 1][lkq * 4 + c][row] = pb[s].f[c];
            }
        }
        __syncthreads();
        buf ^= 1;
    }
    #pragma unroll
    for (int kk = 0; kk < 16; kk++) {
        F4 a0, a1, b0, b1;
        a0.v = *reinterpret_cast<const float4*>(&As[buf][kk][tm]);
        a1.v = *reinterpret_cast<const float4*>(&As[buf][kk][tm + 4]);
        b0.v = *reinterpret_cast<const float4*>(&Bs[buf][kk][tn]);
        b1.v = *reinterpret_cast<const float4*>(&Bs[buf][kk][tn + 4]);
        #pragma unroll
        for (int i = 0; i < 8; i++) {
            ull aa = pack2(i < 4 ? a0.f[i] : a1.f[i - 4]);
            fma2(acc[i][0], aa, b0.u[0]);
            fma2(acc[i][1], aa, b0.u[1]);
            fma2(acc[i][2], aa, b1.u[0]);
            fma2(acc[i][3], aa, b1.u[1]);
        }
    }

    #pragma unroll
    for (int i = 0; i < 8; i++) {
        int gm = mBase + tm + i;
        if (gm >= M) continue;
        #pragma unroll
        for (int jh = 0; jh < 2; jh++) {
            int gn = nBase + tn + jh * 4;
            if (gn >= N) continue;
            U2 p0, p1; p0.u = acc[i][jh * 2]; p1.u = acc[i][jh * 2 + 1];
            float4 v = make_float4(p0.f.x * alpha, p0.f.y * alpha,
                                   p1.f.x * alpha, p1.f.y * alpha);
            if (bias) {
                float4 bb = *reinterpret_cast<const float4*>(bias + gn);
                v.x += bb.x; v.y += bb.y; v.z += bb.z; v.w += bb.w;
            }
            *reinterpret_cast<float4*>(C + (size_t)gm * ldc + gn) = v;
        }
    }
}

// ---------------------------------------------------------------------------
// softmax row stats over G (reads raw scores); stores m and 1/sumexp
// ---------------------------------------------------------------------------
__global__ __launch_bounds__(256) void softmax_stats_kernel(const float* __restrict__ S)
{
    const int row = blockIdx.x;
    const float4* s4 = reinterpret_cast<const float4*>(S + (size_t)row * NG);
    const int tid = threadIdx.x;

    float m = -1e30f, l = 0.f;
    for (int i = tid; i < NG / 4; i += 256) {
        float4 x = s4[i];
        float mx = fmaxf(fmaxf(x.x, x.y), fmaxf(x.z, x.w));
        float mn = fmaxf(m, mx);
        l = l * __expf(m - mn) + __expf(x.x - mn) + __expf(x.y - mn)
                               + __expf(x.z - mn) + __expf(x.w - mn);
        m = mn;
    }
    __shared__ float sm[256], sl[256];
    sm[tid] = m; sl[tid] = l;
    __syncthreads();
    for (int off = 128; off; off >>= 1) {
        if (tid < off) {
            float m2 = sm[tid + off], l2 = sl[tid + off];
            float mn = fmaxf(sm[tid], m2);
            sl[tid] = sl[tid] * __expf(sm[tid] - mn) + l2 * __expf(m2 - mn);
            sm[tid] = mn;
        }
        __syncthreads();
    }
    if (tid == 0) { g_m[row] = sm[0]; g_l[row] = 1.f / sl[0]; }
}

// ---------------------------------------------------------------------------
// normalize raw scores IN PLACE (runs after PV has consumed the raw scores)
// ---------------------------------------------------------------------------
__global__ __launch_bounds__(256) void softmax_norm_kernel(float* __restrict__ S)
{
    const int row = blockIdx.y;
    const float m    = g_m[row];
    const float invl = g_l[row];
    const int i4 = blockIdx.x * 256 + threadIdx.x;
    if (i4 < NG / 4) {
        float4* p = reinterpret_cast<float4*>(S + (size_t)row * NG) + i4;
        *p = expf4(*p, m, invl);
    }
}

// ---------------------------------------------------------------------------
// PV with fused softmax: part[h,ks][b][d] = sum_g exp(S[b,h,g]-m)*invl * V[g,h*64+d]
// Reads RAW scores (S) + stats. 128(b) x 64(d) tile, 256 threads, 4x8 microtile.
// Grid: (2, 1, NH*KS)
// ---------------------------------------------------------------------------
__global__ __launch_bounds__(256, 2) void pv_kernel(
    const float* __restrict__ S, const float* __restrict__ V, float* __restrict__ part)
{
    const int h  = blockIdx.z / KS;
    const int ks = blockIdx.z % KS;
    const int tid = threadIdx.x;
    const int mBase = blockIdx.x * 128;
    const int kbeg = ks * KCHUNK;
    const int kend = min(kbeg + KCHUNK, NG);
    const int nIter = (kend - kbeg) / 16;

    __shared__ __align__(16) float As[2][16][128];
    __shared__ __align__(16) float Bs[2][16][64];

    const int tm = (tid >> 3) * 4;   // 0..124
    const int tn = (tid & 7) * 8;    // 0..56

    const int lrow = tid >> 2, lkq = tid & 3;
    const float* sPtr[2]; float mrow[2], lrowv[2];
    #pragma unroll
    for (int s = 0; s < 2; s++) {
        int b = mBase + lrow + s * 64;
        sPtr[s] = S + (size_t)b * (NH * NG) + (size_t)h * NG + kbeg + lkq * 4;
        mrow[s]  = g_m[b * NH + h];
        lrowv[s] = g_l[b * NH + h];
    }
    const int lkr = tid >> 4, ldq = tid & 15;
    const float* vPtr = V + (size_t)(kbeg + lkr) * NL + h * NHD + ldq * 4;

    ull acc[4][4];
    #pragma unroll
    for (int i = 0; i < 4; i++)
        #pragma unroll
        for (int j = 0; j < 4; j++) acc[i][j] = 0ull;

    F4 pa[2], pb;

    #pragma unroll
    for (int s = 0; s < 2; s++) {
        pa[s].v = expf4(*reinterpret_cast<const float4*>(sPtr[s]), mrow[s], lrowv[s]);
        sPtr[s] += 16;
    }
    pb.v = *reinterpret_cast<const float4*>(vPtr); vPtr += 16 * NL;
    #pragma unroll
    for (int s = 0; s < 2; s++) {
        int row = lrow + s * 64;
        #pragma unroll
        for (int c = 0; c < 4; c++) As[0][lkq * 4 + c][row] = pa[s].f[c];
    }
    *reinterpret_cast<float4*>(&Bs[0][lkr][ldq * 4]) = pb.v;
    __syncthreads();

    int buf = 0;
    for (int it = 1; it < nIter; it++) {
        #pragma unroll
        for (int s = 0; s < 2; s++) {
            pa[s].v = expf4(*reinterpret_cast<const float4*>(sPtr[s]), mrow[s], lrowv[s]);
            sPtr[s] += 16;
        }
        pb.v = *reinterpret_cast<const float4*>(vPtr); vPtr += 16 * NL;

        #pragma unroll
        for (int kk = 0; kk < 16; kk++) {
            F4 a0, b0, b1;
            a0.v = *reinterpret_cast<const float4*>(&As[buf][kk][tm]);
            b0.v = *reinterpret_cast<const float4*>(&Bs[buf][kk][tn]);
            b1.v = *reinterpret_cast<const float4*>(&Bs[buf][kk][tn + 4]);
            #pragma unroll
            for (int i = 0; i < 4; i++) {
                ull aa = pack2(a0.f[i]);
                fma2(acc[i][0], aa, b0.u[0]);
                fma2(acc[i][1], aa, b0.u[1]);
                fma2(acc[i][2], aa, b1.u[0]);
                fma2(acc[i][3], aa, b1.u[1]);
            }
        }
        #pragma unroll
        for (int s = 0; s < 2; s++) {
            int row = lrow + s * 64;
            #pragma unroll
            for (int c = 0; c < 4; c++) As[buf ^ 1][lkq * 4 + c][row] = pa[s].f[c];
        }
        *reinterpret_cast<float4*>(&Bs[buf ^ 1][lkr][ldq * 4]) = pb.v;
        __syncthreads();
        buf ^= 1;
    }
    #pragma unroll
    for (int kk = 0; kk < 16; kk++) {
        F4 a0, b0, b1;
        a0.v = *reinterpret_cast<const float4*>(&As[buf][kk][tm]);
        b0.v = *reinterpret_cast<const float4*>(&Bs[buf][kk][tn]);
        b1.v = *reinterpret_cast<const float4*>(&Bs[buf][kk][tn + 4]);
        #pragma unroll
        for (int i = 0; i < 4; i++) {
            ull aa = pack2(a0.f[i]);
            fma2(acc[i][0], aa, b0.u[0]);
            fma2(acc[i][1], aa, b0.u[1]);
            fma2(acc[i][2], aa, b1.u[0]);
            fma2(acc[i][3], aa, b1.u[1]);
        }
    }

    float* Cp = part + ((size_t)blockIdx.z * NB + mBase) * NHD;
    #pragma unroll
    for (int i = 0; i < 4; i++) {
        #pragma unroll
        for (int jh = 0; jh < 2; jh++) {
            U2 p0, p1; p0.u = acc[i][jh * 2]; p1.u = acc[i][jh * 2 + 1];
            float4 v = make_float4(p0.f.x, p0.f.y, p1.f.x, p1.f.y);
            *reinterpret_cast<float4*>(Cp + (size_t)(tm + i) * NHD + tn + jh * 4) = v;
        }
    }
}

// reduce PV partials (KS chunks) -> ctx
__global__ __launch_bounds__(256) void pv_reduce_kernel(
    const float* __restrict__ part, float* __restrict__ ctx)
{
    const int idx = blockIdx.x * 256 + threadIdx.x;
    const int b = idx >> 9, c = idx & 511;
    const int h = c >> 6, d = c & 63;
    float s = 0.f;
    #pragma unroll
    for (int ks = 0; ks < KS; ks++)
        s += part[(((size_t)(h * KS + ks)) * NB + b) * NHD + d];
    ctx[idx] = s;
}

// reduce Q split-K partials + bias
__global__ __launch_bounds__(256) void q_reduce_kernel(
    const float* __restrict__ qp, const float* __restrict__ bq, float* __restrict__ Q)
{
    const int idx = blockIdx.x * 256 + threadIdx.x;  // < NB*NL
    float s = bq[idx & (NL - 1)];
    #pragma unroll
    for (int z = 0; z < QSK; z++) s += qp[(size_t)z * NB * NL + idx];
    Q[idx] = s;
}

// h1 split-K reduce + bias + LayerNorm + ReLU -> g_h1
__global__ __launch_bounds__(256) void ln_relu_kernel(
    const float* __restrict__ hp, const float* __restrict__ b1,
    const float* __restrict__ g, const float* __restrict__ bt, float* __restrict__ hout)
{
    const int b = blockIdx.x;
    const int tid = threadIdx.x;
    float x0 = b1[tid], x1 = b1[tid + 256];
    #pragma unroll
    for (int z = 0; z < QSK; z++) {
        x0 += hp[(size_t)z * NB * NL + (size_t)b * NL + tid];
        x1 += hp[(size_t)z * NB * NL + (size_t)b * NL + tid + 256];
    }
    __shared__ float s1[256], s2[256];
    s1[tid] = x0 + x1;
    s2[tid] = x0 * x0 + x1 * x1;
    __syncthreads();
    for (int off = 128; off; off >>= 1) {
        if (tid < off) { s1[tid] += s1[tid + off]; s2[tid] += s2[tid + off]; }
        __syncthreads();
    }
    const float mu  = s1[0] * (1.f / 512.f);
    const float var = s2[0] * (1.f / 512.f) - mu * mu;
    const float rs  = rsqrtf(var + 1e-5f);
    float y0 = (x0 - mu) * rs * g[tid]       + bt[tid];
    float y1 = (x1 - mu) * rs * g[tid + 256] + bt[tid + 256];
    hout[(size_t)b * NL + tid]       = fmaxf(y0, 0.f);
    hout[(size_t)b * NL + tid + 256] = fmaxf(y1, 0.f);
}

// ---------------------------------------------------------------------------
extern "C" void kernel_launch(void* const* d_in, const int* in_sizes, int n_in,
                              void* d_out, int out_size)
{
    const float* z   = (const float*)d_in[0];
    const float* E   = (const float*)d_in[1];
    const float* Wq  = (const float*)d_in[2];
    const float* bq  = (const float*)d_in[3];
    const float* Wk  = (const float*)d_in[4];
    const float* bk  = (const float*)d_in[5];
    const float* Wv  = (const float*)d_in[6];
    const float* bv  = (const float*)d_in[7];
    const float* W1  = (const float*)d_in[8];
    const float* b1  = (const float*)d_in[9];
    const float* lng = (const float*)d_in[10];
    const float* lnb = (const float*)d_in[11];
    const float* W2  = (const float*)d_in[12];
    const float* b2  = (const float*)d_in[13];

    float* out  = (float*)d_out;
    float* ga   = out;                          // gene_attention [NB, NG]
    float* attn = out + (size_t)NB * NG;        // attn [NB, NH, NG] (raw scores first)

    float *pK, *pV, *pQ, *pCtx, *pH1, *pPart, *pQp, *pHp;
    cudaGetSymbolAddress((void**)&pK,    g_K);
    cudaGetSymbolAddress((void**)&pV,    g_V);
    cudaGetSymbolAddress((void**)&pQ,    g_Q);
    cudaGetSymbolAddress((void**)&pCtx,  g_ctx);
    cudaGetSymbolAddress((void**)&pH1,   g_h1);
    cudaGetSymbolAddress((void**)&pPart, g_part);
    cudaGetSymbolAddress((void**)&pQp,   g_qp);
    cudaGetSymbolAddress((void**)&pHp,   g_hp);

    const int gTiles = (NG + 127) / 128;   // 157

    // Q partial = z @ Wq^T (split-K over z-dim, 128 k per slice)
    sgemm_nt<<<dim3(2, 4, QSK), 256>>>(z, Wq, pQp, nullptr,
        NB, NL, NL / QSK, NL, NL, NL, 128, 128, (long long)NB * NL, 1.f);
    q_reduce_kernel<<<(NB * NL) / 256, 256>>>(pQp, bq, pQ);
    // K, V projections
    sgemm_nt<<<dim3(gTiles, 4, 1), 256>>>(E, Wk, pK, bk,
        NG, NL, ND, ND, ND, NL, 0, 0, 0, 1.f);
    sgemm_nt<<<dim3(gTiles, 4, 1), 256>>>(E, Wv, pV, bv,
        NG, NL, ND, ND, ND, NL, 0, 0, 0, 1.f);
    // raw scores -> attn region of d_out
    sgemm_nt<<<dim3(2, gTiles, NH), 256>>>(pQ, pK, attn, nullptr,
        NB, NG, NHD, NL, NL, (long long)NH * NG,
        NHD, NHD, (long long)NG, ATT_SCALE);
    // softmax stats over raw scores
    softmax_stats_kernel<<<NB * NH, 256>>>(attn);
    // PV consumes RAW scores with fused exp (stream-ordered before norm)
    pv_kernel<<<dim3(2, 1, NH * KS), 256>>>(attn, pV, pPart);
    pv_reduce_kernel<<<(NB * NL) / 256, 256>>>(pPart, pCtx);
    // now normalize attn in place (raw -> softmax output)
    softmax_norm_kernel<<<dim3((NG / 4 + 255) / 256, NB * NH), 256>>>(attn);
    // h1 partial = ctx @ W1^T (split-K), then fused reduce+LN+ReLU
    sgemm_nt<<<dim3(2, 4, QSK), 256>>>(pCtx, W1, pHp, nullptr,
        NB, NL, NL / QSK, NL, NL, NL, 128, 128, (long long)NB * NL, 1.f);
    ln_relu_kernel<<<NB, 256>>>(pHp, b1, lng, lnb, pH1);
    // gene_attention = h1 @ W2^T + b2
    sgemm_nt<<<dim3(2, gTiles, 1), 256>>>(pH1, W2, ga, b2,
        NB, NG, NL, NL, NL, (long long)NG, 0, 0, 0, 1.f);
}

// round 7
// speedup vs baseline: 1.6015x; 1.1874x over previous
#include <cuda_runtime.h>
#include <cuda_bf16.h>

typedef unsigned int u32;
typedef unsigned long long ull;
typedef __nv_bfloat16 bf16;

constexpr int NB = 256, NG = 20000, NL = 512, ND = 256, NH = 8;
constexpr float ATT_SCALE = 0.125f;
constexpr int PVKS = 10, PVCH = 2048;
constexpr int GEMM_SMEM = 1024 + 2 * 65536;   // 132096
constexpr int PV_SMEM   = 1024 + 49152;       // 50176

// -------- static scratch (~150 MB) --------
__device__ bf16 g_Eh[(size_t)NG * ND],  g_El[(size_t)NG * ND];
__device__ bf16 g_W2h[(size_t)NG * NL], g_W2l[(size_t)NG * NL];
__device__ bf16 g_Kh[(size_t)NG * NL],  g_Kl[(size_t)NG * NL];
__device__ bf16 g_Vth[(size_t)NL * NG], g_Vtl[(size_t)NL * NG];
__device__ bf16 g_Wqh[NL * NL], g_Wql[NL * NL];
__device__ bf16 g_Wkh[NL * ND], g_Wkl[NL * ND];
__device__ bf16 g_Wvh[NL * ND], g_Wvl[NL * ND];
__device__ bf16 g_W1h[NL * NL], g_W1l[NL * NL];
__device__ bf16 g_zh[NB * NL],  g_zl[NB * NL];
__device__ bf16 g_Qh[NB * NL],  g_Ql[NB * NL];
__device__ bf16 g_ch[NB * NL],  g_cl[NB * NL];
__device__ bf16 g_h1h[NB * NL], g_h1l[NB * NL];
__device__ float g_h1f[NB * NL];
__device__ float g_m[NB * NH], g_l[NB * NH];
__device__ float g_part[PVKS * NB * NL];

// -------- helpers --------
__device__ __forceinline__ u32 s2u(const void* p) {
    u32 a; asm("{ .reg .u64 t; cvta.to.shared.u64 t, %1; cvt.u32.u64 %0, t; }" : "=r"(a) : "l"(p));
    return a;
}
__device__ __forceinline__ void ldsm4(u32* r, u32 a) {
    asm volatile("ldmatrix.sync.aligned.m8n8.x4.shared.b16 {%0,%1,%2,%3}, [%4];"
        : "=r"(r[0]), "=r"(r[1]), "=r"(r[2]), "=r"(r[3]) : "r"(a));
}
__device__ __forceinline__ void mma16816(float* d, const u32* a, const u32* b) {
    asm volatile("mma.sync.aligned.m16n8k16.row.col.f32.bf16.bf16.f32 "
        "{%0,%1,%2,%3}, {%4,%5,%6,%7}, {%8,%9}, {%0,%1,%2,%3};"
        : "+f"(d[0]), "+f"(d[1]), "+f"(d[2]), "+f"(d[3])
        : "r"(a[0]), "r"(a[1]), "r"(a[2]), "r"(a[3]), "r"(b[0]), "r"(b[1]));
}
__device__ __forceinline__ void cpasync16(u32 dst, const void* src, int srcsz) {
    asm volatile("cp.async.cg.shared.global [%0], [%1], 16, %2;"
        :: "r"(dst), "l"(src), "r"(srcsz) : "memory");
}
#define CP_COMMIT() asm volatile("cp.async.commit_group;" ::: "memory")
#define CP_WAIT0()  asm volatile("cp.async.wait_group 0;" ::: "memory")
#define CP_WAIT1()  asm volatile("cp.async.wait_group 1;" ::: "memory")

__device__ __forceinline__ u32 swz(u32 o) { return o ^ ((o >> 3) & 0x70); }
__device__ __forceinline__ void split2(float v, bf16& h, bf16& l) {
    h = __float2bfloat16(v);
    l = __float2bfloat16(v - __bfloat162float(h));
}
union BQ { bf16 b[4]; uint2 u; };

// async bf16 tile loader: rows x 64k, SW128 swizzled, zero-filled OOB
__device__ __forceinline__ void ld_tile_async(char* sm, u32 off, const bf16* __restrict__ src,
    long long ld, int rowBase, int rowMax, long long kBase, long long kMax, int rows, int tid)
{
    for (int f = tid; f < rows * 8; f += 256) {
        int r = f >> 3, ch = f & 7;
        int gr = rowBase + r;
        bool ok = (gr < rowMax) && (kBase + ch * 8 < kMax);
        const bf16* g = src + (size_t)(ok ? gr : rowBase) * ld + kBase + (ok ? ch * 8 : 0);
        cpasync16(s2u(sm + off + swz((u32)(r * 128 + ch * 16))), g, ok ? 16 : 0);
    }
}
// synchronous variant (PV B tiles)
__device__ __forceinline__ void ld_tile(char* sm, u32 off, const bf16* __restrict__ src,
    long long ld, int rowBase, int rowMax, long long kBase, long long kMax, int rows, int tid)
{
    const uint4 z = make_uint4(0, 0, 0, 0);
    for (int f = tid; f < rows * 8; f += 256) {
        int r = f >> 3, ch = f & 7;
        int gr = rowBase + r;
        uint4 v = (gr < rowMax && kBase + ch * 8 < kMax)
            ? *(const uint4*)(src + (size_t)gr * ld + kBase + ch * 8) : z;
        *(uint4*)(sm + off + swz((u32)(r * 128 + ch * 16))) = v;
    }
}

// ===========================================================================
// HMMA GEMM NT: C = alpha*(Ah.Bh + Ah.Bl + Al.Bh) + bias
// 128x128 tile, K-slab 64 (K%64==0), 256 threads = 8 warps (4x2), warp 32x64.
// mode 0: fp32 C[gm*ldc+n]; 1: bf16 split out[gm*ldo+n]; 2: transposed split.
// zk: per-z k-offset; cZs: C z-offset.
// ===========================================================================
__global__ __launch_bounds__(256, 1) void hm_gemm(
    const bf16* __restrict__ Ah, const bf16* __restrict__ Al,
    const bf16* __restrict__ Bh, const bf16* __restrict__ Bl,
    float* __restrict__ C, bf16* __restrict__ outH, bf16* __restrict__ outL,
    const float* __restrict__ bias,
    int M, int N, int K, int lda, int ldb, long long ldc, long long ldo,
    int zk, long long cZs, float alpha, int mode)
{
    extern __shared__ char sm[];
    const int tid = threadIdx.x, lane = tid & 31, w = tid >> 5;
    const int wm = w >> 1, wn = w & 1;
    const int mBase = blockIdx.x * 128, nBase = blockIdx.y * 128;
    const long long kOff = (long long)zk * blockIdx.z;
    C += (size_t)blockIdx.z * cZs;

    float acc[2][8][4];
    #pragma unroll
    for (int t = 0; t < 2; t++)
        #pragma unroll
        for (int j = 0; j < 8; j++)
            #pragma unroll
            for (int q = 0; q < 4; q++) acc[t][j][q] = 0.f;

    const int ns = K / 64;
    // prologue: slab 0 -> buf 0
    {
        long long kB = kOff;
        ld_tile_async(sm, 1024,         Ah, lda, mBase, M, kB, 1LL << 60, 128, tid);
        ld_tile_async(sm, 1024 + 16384, Al, lda, mBase, M, kB, 1LL << 60, 128, tid);
        ld_tile_async(sm, 1024 + 32768, Bh, ldb, nBase, N, kB, 1LL << 60, 128, tid);
        ld_tile_async(sm, 1024 + 49152, Bl, ldb, nBase, N, kB, 1LL << 60, 128, tid);
        CP_COMMIT();
    }
    const u32 rsel = lane & 15, csel = (u32)((lane >> 4) << 4);
    for (int s = 0; s < ns; s++) {
        if (s + 1 < ns) {
            u32 bo2 = 1024 + ((s + 1) & 1) * 65536;
            long long kB = kOff + (long long)(s + 1) * 64;
            ld_tile_async(sm, bo2,         Ah, lda, mBase, M, kB, 1LL << 60, 128, tid);
            ld_tile_async(sm, bo2 + 16384, Al, lda, mBase, M, kB, 1LL << 60, 128, tid);
            ld_tile_async(sm, bo2 + 32768, Bh, ldb, nBase, N, kB, 1LL << 60, 128, tid);
            ld_tile_async(sm, bo2 + 49152, Bl, ldb, nBase, N, kB, 1LL << 60, 128, tid);
            CP_COMMIT();
            CP_WAIT1();
        } else {
            CP_WAIT0();
        }
        __syncthreads();
        const u32 bo = 1024 + (s & 1) * 65536;
        const u32 aH = s2u(sm + bo), aL = aH + 16384, bH = aH + 32768, bL = aH + 49152;
        #pragma unroll
        for (int kk = 0; kk < 4; kk++) {
            const u32 cb = kk * 32 + csel;
            u32 ah[2][4], al[2][4];
            #pragma unroll
            for (int t = 0; t < 2; t++) {
                u32 o = swz((u32)((wm * 32 + t * 16 + rsel) * 128) + cb);
                ldsm4(ah[t], aH + o);
                ldsm4(al[t], aL + o);
            }
            u32 bh[8][2], bl[8][2];
            #pragma unroll
            for (int u = 0; u < 4; u++) {
                u32 o = swz((u32)((wn * 64 + u * 16 + rsel) * 128) + cb);
                u32 m[4], ml[4];
                ldsm4(m, bH + o); ldsm4(ml, bL + o);
                bh[2*u][0] = m[0];  bh[2*u][1] = m[2];
                bh[2*u+1][0] = m[1]; bh[2*u+1][1] = m[3];
                bl[2*u][0] = ml[0];  bl[2*u][1] = ml[2];
                bl[2*u+1][0] = ml[1]; bl[2*u+1][1] = ml[3];
            }
            #pragma unroll
            for (int t = 0; t < 2; t++)
                #pragma unroll
                for (int j = 0; j < 8; j++) {
                    mma16816(acc[t][j], ah[t], bh[j]);
                    mma16816(acc[t][j], ah[t], bl[j]);
                    mma16816(acc[t][j], al[t], bh[j]);
                }
        }
        __syncthreads();
    }

    // stage fp32 (alpha + bias applied), then coalesced mode stores
    float* stg = (float*)(sm + 1024);
    #pragma unroll
    for (int t = 0; t < 2; t++)
        #pragma unroll
        for (int j = 0; j < 8; j++) {
            int r0 = wm * 32 + t * 16 + (lane >> 2);
            int c0 = wn * 64 + j * 8 + 2 * (lane & 3);
            float b0 = 0.f, b1 = 0.f;
            if (bias) {
                if (nBase + c0 < N)     b0 = bias[nBase + c0];
                if (nBase + c0 + 1 < N) b1 = bias[nBase + c0 + 1];
            }
            stg[r0 * 128 + c0]           = acc[t][j][0] * alpha + b0;
            stg[r0 * 128 + c0 + 1]       = acc[t][j][1] * alpha + b1;
            stg[(r0 + 8) * 128 + c0]     = acc[t][j][2] * alpha + b0;
            stg[(r0 + 8) * 128 + c0 + 1] = acc[t][j][3] * alpha + b1;
        }
    __syncthreads();
    if (mode == 0) {
        for (int i = tid; i < 128 * 32; i += 256) {
            int r = i >> 5, c4 = (i & 31) * 4;
            int gm = mBase + r, n = nBase + c4;
            if (gm < M && n < N)
                *(float4*)(C + (size_t)gm * ldc + n) = *(float4*)(stg + r * 128 + c4);
        }
    } else if (mode == 1) {
        for (int i = tid; i < 128 * 32; i += 256) {
            int r = i >> 5, c4 = (i & 31) * 4;
            int gm = mBase + r, n = nBase + c4;
            if (gm < M && n < N) {
                float4 v = *(float4*)(stg + r * 128 + c4);
                BQ H, L;
                split2(v.x, H.b[0], L.b[0]); split2(v.y, H.b[1], L.b[1]);
                split2(v.z, H.b[2], L.b[2]); split2(v.w, H.b[3], L.b[3]);
                *(uint2*)(outH + (size_t)gm * ldo + n) = H.u;
                *(uint2*)(outL + (size_t)gm * ldo + n) = L.u;
            }
        }
    } else {
        for (int i = tid; i < 128 * 32; i += 256) {
            int c = i >> 5, g4 = (i & 31) * 4;
            int on = nBase + c, og = mBase + g4;
            if (on < N && og < M) {
                float v0 = stg[(g4 + 0) * 128 + c], v1 = stg[(g4 + 1) * 128 + c];
                float v2 = stg[(g4 + 2) * 128 + c], v3 = stg[(g4 + 3) * 128 + c];
                BQ H, L;
                split2(v0, H.b[0], L.b[0]); split2(v1, H.b[1], L.b[1]);
                split2(v2, H.b[2], L.b[2]); split2(v3, H.b[3], L.b[3]);
                *(uint2*)(outH + (size_t)on * ldo + og) = H.u;
                *(uint2*)(outL + (size_t)on * ldo + og) = L.u;
            }
        }
    }
}

// ===========================================================================
// PV HMMA: part[ch][b][h*64+d] = sum_g softmax(S)[b,h,g] * Vt[h*64+d][g]
// Block 128(b) x 64(d), warps 4x2, warp 32x32. A from raw fp32 scores with
// fused exp + bf16 split. Grid (2, NH, PVKS). Single-buffer synchronous.
// ===========================================================================
__global__ __launch_bounds__(256, 1) void hm_pv(
    const float* __restrict__ S, const bf16* __restrict__ Vth,
    const bf16* __restrict__ Vtl, float* __restrict__ part)
{
    extern __shared__ char sm[];
    const int tid = threadIdx.x, lane = tid & 31, w = tid >> 5;
    const int wm = w >> 1, wn = w & 1;
    const int mBase = blockIdx.x * 128, h = blockIdx.y, ch = blockIdx.z;
    const long long kbeg = (long long)ch * PVCH;
    const long long kend = (kbeg + PVCH < NG) ? kbeg + PVCH : NG;
    const int ns = (int)((kend - kbeg + 63) / 64);

    float acc[2][4][4];
    #pragma unroll
    for (int t = 0; t < 2; t++)
        #pragma unroll
        for (int j = 0; j < 4; j++)
            #pragma unroll
            for (int q = 0; q < 4; q++) acc[t][j][q] = 0.f;

    const u32 rsel = lane & 15, csel = (u32)((lane >> 4) << 4);
    for (int s = 0; s < ns; s++) {
        long long kB = kbeg + (long long)s * 64;
        __syncthreads();
        // A: exp-split loader (128 rows x 64k)
        for (int f = tid; f < 128 * 16; f += 256) {
            int r = f >> 4, c4 = f & 15;
            int b = mBase + r;
            long long g = kB + c4 * 4;
            bool ok = g < kend;
            float4 v = ok ? *(const float4*)(S + (size_t)b * (NH * NG) + (size_t)h * NG + g)
                          : make_float4(0.f, 0.f, 0.f, 0.f);
            float m = g_m[b * NH + h], il = g_l[b * NH + h];
            float e0 = ok ? __expf(v.x - m) * il : 0.f;
            float e1 = ok ? __expf(v.y - m) * il : 0.f;
            float e2 = ok ? __expf(v.z - m) * il : 0.f;
            float e3 = ok ? __expf(v.w - m) * il : 0.f;
            BQ H, L;
            split2(e0, H.b[0], L.b[0]); split2(e1, H.b[1], L.b[1]);
            split2(e2, H.b[2], L.b[2]); split2(e3, H.b[3], L.b[3]);
            u32 o = swz((u32)(r * 128 + c4 * 8));
            *(uint2*)(sm + 1024 + o) = H.u;
            *(uint2*)(sm + 1024 + 16384 + o) = L.u;
        }
        // B: Vt rows h*64..+64 (64 rows x 64k)
        ld_tile(sm, 1024 + 32768, Vth, NG, h * 64, NL, kB, kend, 64, tid);
        ld_tile(sm, 1024 + 40960, Vtl, NG, h * 64, NL, kB, kend, 64, tid);
        __syncthreads();
        const u32 aH = s2u(sm + 1024), aL = aH + 16384, bH = aH + 32768, bL = aH + 40960;
        #pragma unroll
        for (int kk = 0; kk < 4; kk++) {
            const u32 cb = kk * 32 + csel;
            u32 ah[2][4], al[2][4];
            #pragma unroll
            for (int t = 0; t < 2; t++) {
                u32 o = swz((u32)((wm * 32 + t * 16 + rsel) * 128) + cb);
                ldsm4(ah[t], aH + o);
                ldsm4(al[t], aL + o);
            }
            u32 bh[4][2], bl[4][2];
            #pragma unroll
            for (int u = 0; u < 2; u++) {
                u32 o = swz((u32)((wn * 32 + u * 16 + rsel) * 128) + cb);
                u32 m[4], ml[4];
                ldsm4(m, bH + o); ldsm4(ml, bL + o);
                bh[2*u][0] = m[0];  bh[2*u][1] = m[2];
                bh[2*u+1][0] = m[1]; bh[2*u+1][1] = m[3];
                bl[2*u][0] = ml[0];  bl[2*u][1] = ml[2];
                bl[2*u+1][0] = ml[1]; bl[2*u+1][1] = ml[3];
            }
            #pragma unroll
            for (int t = 0; t < 2; t++)
                #pragma unroll
                for (int j = 0; j < 4; j++) {
                    mma16816(acc[t][j], ah[t], bh[j]);
                    mma16816(acc[t][j], ah[t], bl[j]);
                    mma16816(acc[t][j], al[t], bh[j]);
                }
        }
    }
    __syncthreads();

    float* stg = (float*)(sm + 1024);
    #pragma unroll
    for (int t = 0; t < 2; t++)
        #pragma unroll
        for (int j = 0; j < 4; j++) {
            int r0 = wm * 32 + t * 16 + (lane >> 2);
            int c0 = wn * 32 + j * 8 + 2 * (lane & 3);
            stg[r0 * 64 + c0]           = acc[t][j][0];
            stg[r0 * 64 + c0 + 1]       = acc[t][j][1];
            stg[(r0 + 8) * 64 + c0]     = acc[t][j][2];
            stg[(r0 + 8) * 64 + c0 + 1] = acc[t][j][3];
        }
    __syncthreads();
    for (int i = tid; i < 128 * 16; i += 256) {
        int r = i >> 4, c4 = (i & 15) * 4;
        *(float4*)(part + ((size_t)ch * NB + mBase + r) * NL + h * 64 + c4)
            = *(float4*)(stg + r * 64 + c4);
    }
}

// -------- small kernels --------
__global__ __launch_bounds__(256) void split_kernel(
    const float* __restrict__ s, bf16* __restrict__ oh, bf16* __restrict__ ol, long long n4)
{
    long long i = (long long)blockIdx.x * 256 + threadIdx.x;
    long long st = (long long)gridDim.x * 256;
    for (; i < n4; i += st) {
        float4 v = ((const float4*)s)[i];
        BQ H, L;
        split2(v.x, H.b[0], L.b[0]); split2(v.y, H.b[1], L.b[1]);
        split2(v.z, H.b[2], L.b[2]); split2(v.w, H.b[3], L.b[3]);
        ((uint2*)oh)[i] = H.u; ((uint2*)ol)[i] = L.u;
    }
}

__global__ __launch_bounds__(256) void softmax_stats_kernel(const float* __restrict__ S)
{
    const int row = blockIdx.x;
    const float4* s4 = (const float4*)(S + (size_t)row * NG);
    const int tid = threadIdx.x;
    float m = -1e30f, l = 0.f;
    for (int i = tid; i < NG / 4; i += 256) {
        float4 x = s4[i];
        float mx = fmaxf(fmaxf(x.x, x.y), fmaxf(x.z, x.w));
        float mn = fmaxf(m, mx);
        l = l * __expf(m - mn) + __expf(x.x - mn) + __expf(x.y - mn)
                               + __expf(x.z - mn) + __expf(x.w - mn);
        m = mn;
    }
    __shared__ float sm_[256], sl[256];
    sm_[tid] = m; sl[tid] = l;
    __syncthreads();
    for (int off = 128; off; off >>= 1) {
        if (tid < off) {
            float m2 = sm_[tid + off], l2 = sl[tid + off];
            float mn = fmaxf(sm_[tid], m2);
            sl[tid] = sl[tid] * __expf(sm_[tid] - mn) + l2 * __expf(m2 - mn);
            sm_[tid] = mn;
        }
        __syncthreads();
    }
    if (tid == 0) { g_m[row] = sm_[0]; g_l[row] = 1.f / sl[0]; }
}

__global__ __launch_bounds__(256) void softmax_norm_kernel(float* __restrict__ S)
{
    const int row = blockIdx.y;
    const float m = g_m[row], il = g_l[row];
    const int i4 = blockIdx.x * 256 + threadIdx.x;
    if (i4 < NG / 4) {
        float4* p = (float4*)(S + (size_t)row * NG) + i4;
        float4 v = *p;
        v.x = __expf(v.x - m) * il; v.y = __expf(v.y - m) * il;
        v.z = __expf(v.z - m) * il; v.w = __expf(v.w - m) * il;
        *p = v;
    }
}

__global__ __launch_bounds__(256) void pv_reduce_split(
    const float* __restrict__ part, bf16* __restrict__ oh, bf16* __restrict__ ol)
{
    const int idx = blockIdx.x * 256 + threadIdx.x;
    float s = 0.f;
    #pragma unroll
    for (int c = 0; c < PVKS; c++) s += part[(size_t)c * NB * NL + idx];
    bf16 h, l; split2(s, h, l);
    oh[idx] = h; ol[idx] = l;
}

__global__ __launch_bounds__(256) void ln_relu_split(
    const float* __restrict__ hf, const float* __restrict__ g,
    const float* __restrict__ bt, bf16* __restrict__ oh, bf16* __restrict__ ol)
{
    const int b = blockIdx.x, tid = threadIdx.x;
    float x0 = hf[(size_t)b * NL + tid], x1 = hf[(size_t)b * NL + tid + 256];
    __shared__ float s1[256], s2[256];
    s1[tid] = x0 + x1; s2[tid] = x0 * x0 + x1 * x1;
    __syncthreads();
    for (int off = 128; off; off >>= 1) {
        if (tid < off) { s1[tid] += s1[tid + off]; s2[tid] += s2[tid + off]; }
        __syncthreads();
    }
    const float mu = s1[0] * (1.f / 512.f);
    const float var = s2[0] * (1.f / 512.f) - mu * mu;
    const float rs = rsqrtf(var + 1e-5f);
    float y0 = fmaxf((x0 - mu) * rs * g[tid] + bt[tid], 0.f);
    float y1 = fmaxf((x1 - mu) * rs * g[tid + 256] + bt[tid + 256], 0.f);
    bf16 h, l;
    split2(y0, h, l); oh[(size_t)b * NL + tid] = h;       ol[(size_t)b * NL + tid] = l;
    split2(y1, h, l); oh[(size_t)b * NL + tid + 256] = h; ol[(size_t)b * NL + tid + 256] = l;
}

// ---------------------------------------------------------------------------
extern "C" void kernel_launch(void* const* d_in, const int* in_sizes, int n_in,
                              void* d_out, int out_size)
{
    const float* z   = (const float*)d_in[0];
    const float* E   = (const float*)d_in[1];
    const float* Wq  = (const float*)d_in[2];
    const float* bq  = (const float*)d_in[3];
    const float* Wk  = (const float*)d_in[4];
    const float* bk  = (const float*)d_in[5];
    const float* Wv  = (const float*)d_in[6];
    const float* bv  = (const float*)d_in[7];
    const float* W1  = (const float*)d_in[8];
    const float* b1  = (const float*)d_in[9];
    const float* lng = (const float*)d_in[10];
    const float* lnb = (const float*)d_in[11];
    const float* W2  = (const float*)d_in[12];
    const float* b2  = (const float*)d_in[13];

    float* out  = (float*)d_out;
    float* ga   = out;
    float* attn = out + (size_t)NB * NG;   // raw scores, then softmax in place

    cudaFuncSetAttribute(hm_gemm, cudaFuncAttributeMaxDynamicSharedMemorySize, GEMM_SMEM);
    cudaFuncSetAttribute(hm_pv,   cudaFuncAttributeMaxDynamicSharedMemorySize, PV_SMEM);

    bf16 *Eh, *El, *W2h, *W2l, *Kh, *Kl, *Vth, *Vtl, *Wqh, *Wql, *Wkh, *Wkl,
         *Wvh, *Wvl, *W1h, *W1l, *zh, *zl, *Qh, *Ql, *ch, *cl, *h1h, *h1l;
    float *h1f, *part;
    cudaGetSymbolAddress((void**)&Eh, g_Eh);   cudaGetSymbolAddress((void**)&El, g_El);
    cudaGetSymbolAddress((void**)&W2h, g_W2h); cudaGetSymbolAddress((void**)&W2l, g_W2l);
    cudaGetSymbolAddress((void**)&Kh, g_Kh);   cudaGetSymbolAddress((void**)&Kl, g_Kl);
    cudaGetSymbolAddress((void**)&Vth, g_Vth); cudaGetSymbolAddress((void**)&Vtl, g_Vtl);
    cudaGetSymbolAddress((void**)&Wqh, g_Wqh); cudaGetSymbolAddress((void**)&Wql, g_Wql);
    cudaGetSymbolAddress((void**)&Wkh, g_Wkh); cudaGetSymbolAddress((void**)&Wkl, g_Wkl);
    cudaGetSymbolAddress((void**)&Wvh, g_Wvh); cudaGetSymbolAddress((void**)&Wvl, g_Wvl);
    cudaGetSymbolAddress((void**)&W1h, g_W1h); cudaGetSymbolAddress((void**)&W1l, g_W1l);
    cudaGetSymbolAddress((void**)&zh, g_zh);   cudaGetSymbolAddress((void**)&zl, g_zl);
    cudaGetSymbolAddress((void**)&Qh, g_Qh);   cudaGetSymbolAddress((void**)&Ql, g_Ql);
    cudaGetSymbolAddress((void**)&ch, g_ch);   cudaGetSymbolAddress((void**)&cl, g_cl);
    cudaGetSymbolAddress((void**)&h1h, g_h1h); cudaGetSymbolAddress((void**)&h1l, g_h1l);
    cudaGetSymbolAddress((void**)&h1f, g_h1f); cudaGetSymbolAddress((void**)&part, g_part);

    const int gT = (NG + 127) / 128;   // 157

    split_kernel<<<1024, 256>>>(E,  Eh,  El,  (long long)NG * ND / 4);
    split_kernel<<<1024, 256>>>(W2, W2h, W2l, (long long)NG * NL / 4);
    split_kernel<<<256, 256>>>(Wq, Wqh, Wql, NL * NL / 4);
    split_kernel<<<128, 256>>>(Wk, Wkh, Wkl, NL * ND / 4);
    split_kernel<<<128, 256>>>(Wv, Wvh, Wvl, NL * ND / 4);
    split_kernel<<<256, 256>>>(W1, W1h, W1l, NL * NL / 4);
    split_kernel<<<128, 256>>>(z,  zh,  zl,  NB * NL / 4);

    // K = E@Wk^T + bk -> bf16 split [NG, NL]
    hm_gemm<<<dim3(gT, 4, 1), 256, GEMM_SMEM>>>(Eh, El, Wkh, Wkl, nullptr, Kh, Kl, bk,
        NG, NL, ND, ND, ND, 0, NL, 0, 0, 1.f, 1);
    // Vt = (E@Wv^T + bv)^T -> bf16 split [NL, NG]
    hm_gemm<<<dim3(gT, 4, 1), 256, GEMM_SMEM>>>(Eh, El, Wvh, Wvl, nullptr, Vth, Vtl, bv,
        NG, NL, ND, ND, ND, 0, NG, 0, 0, 1.f, 2);
    // Q = z@Wq^T + bq -> bf16 split [NB, NL]
    hm_gemm<<<dim3(2, 4, 1), 256, GEMM_SMEM>>>(zh, zl, Wqh, Wql, nullptr, Qh, Ql, bq,
        NB, NL, NL, NL, NL, 0, NL, 0, 0, 1.f, 1);
    // raw scores -> attn region (per-head k-offset via z)
    hm_gemm<<<dim3(2, gT, NH), 256, GEMM_SMEM>>>(Qh, Ql, Kh, Kl, attn, nullptr, nullptr, nullptr,
        NB, NG, 64, NL, NL, (long long)NH * NG, 0, 64, (long long)NG, ATT_SCALE, 0);
    // softmax stats, PV (fused exp), reduce, then normalize in place
    softmax_stats_kernel<<<NB * NH, 256>>>(attn);
    hm_pv<<<dim3(2, NH, PVKS), 256, PV_SMEM>>>(attn, Vth, Vtl, part);
    pv_reduce_split<<<(NB * NL) / 256, 256>>>(part, ch, cl);
    softmax_norm_kernel<<<dim3((NG / 4 + 255) / 256, NB * NH), 256>>>(attn);
    // h1 = ctx@W1^T + b1 (fp32), LN+ReLU -> bf16 split
    hm_gemm<<<dim3(2, 4, 1), 256, GEMM_SMEM>>>(ch, cl, W1h, W1l, h1f, nullptr, nullptr, b1,
        NB, NL, NL, NL, NL, NL, 0, 0, 0, 1.f, 0);
    ln_relu_split<<<NB, 256>>>(h1f, lng, lnb, h1h, h1l);
    // gene_attention = h1@W2^T + b2
    hm_gemm<<<dim3(2, gT, 1), 256, GEMM_SMEM>>>(h1h, h1l, W2h, W2l, ga, nullptr, nullptr, b2,
        NB, NG, NL, NL, NL, (long long)NG, 0, 0, 0, 1.f, 0);
}

// round 8
// speedup vs baseline: 1.7655x; 1.1024x over previous
#include <cuda_runtime.h>
#include <cuda_bf16.h>

typedef unsigned int u32;
typedef unsigned long long ull;
typedef __nv_bfloat16 bf16;

constexpr int NB = 256, NG = 20000, NL = 512, ND = 256, NH = 8;
constexpr float ATT_SCALE = 0.125f;
constexpr int PVKS = 18, PVCH = 1152;         // 18*1152 = 20736 >= 20000
constexpr int NT = 160;                        // padded scores-tile count (157 used)
constexpr int GEMM_SMEM   = 1024 + 2 * 65536;  // double-buffered
constexpr int SCORES_SMEM = 1024 + 65536;      // single slab (K=64)
constexpr int PV_SMEM     = 1024 + 49152;

// -------- static scratch --------
__device__ bf16 g_Eh[(size_t)NG * ND],  g_El[(size_t)NG * ND];
__device__ bf16 g_W2h[(size_t)NG * NL], g_W2l[(size_t)NG * NL];
__device__ bf16 g_Kh[(size_t)NG * NL],  g_Kl[(size_t)NG * NL];
__device__ bf16 g_Vth[(size_t)NL * NG], g_Vtl[(size_t)NL * NG];
__device__ bf16 g_Wqh[NL * NL], g_Wql[NL * NL];
__device__ bf16 g_Wkh[NL * ND], g_Wkl[NL * ND];
__device__ bf16 g_Wvh[NL * ND], g_Wvl[NL * ND];
__device__ bf16 g_W1h[NL * NL], g_W1l[NL * NL];
__device__ bf16 g_zh[NB * NL],  g_zl[NB * NL];
__device__ bf16 g_Qh[NB * NL],  g_Ql[NB * NL];
__device__ bf16 g_ch[NB * NL],  g_cl[NB * NL];
__device__ bf16 g_h1h[NB * NL], g_h1l[NB * NL];
__device__ float g_h1f[NB * NL];
__device__ float g_m[NB * NH], g_l[NB * NH];
__device__ float g_pmax[NB * NH * NT], g_psum[NB * NH * NT];
__device__ float g_part[PVKS * NB * NL];

// -------- helpers --------
__device__ __forceinline__ u32 s2u(const void* p) {
    u32 a; asm("{ .reg .u64 t; cvta.to.shared.u64 t, %1; cvt.u32.u64 %0, t; }" : "=r"(a) : "l"(p));
    return a;
}
__device__ __forceinline__ void ldsm4(u32* r, u32 a) {
    asm volatile("ldmatrix.sync.aligned.m8n8.x4.shared.b16 {%0,%1,%2,%3}, [%4];"
        : "=r"(r[0]), "=r"(r[1]), "=r"(r[2]), "=r"(r[3]) : "r"(a));
}
__device__ __forceinline__ void mma16816(float* d, const u32* a, const u32* b) {
    asm volatile("mma.sync.aligned.m16n8k16.row.col.f32.bf16.bf16.f32 "
        "{%0,%1,%2,%3}, {%4,%5,%6,%7}, {%8,%9}, {%0,%1,%2,%3};"
        : "+f"(d[0]), "+f"(d[1]), "+f"(d[2]), "+f"(d[3])
        : "r"(a[0]), "r"(a[1]), "r"(a[2]), "r"(a[3]), "r"(b[0]), "r"(b[1]));
}
__device__ __forceinline__ void cpasync16(u32 dst, const void* src, int srcsz) {
    asm volatile("cp.async.cg.shared.global [%0], [%1], 16, %2;"
        :: "r"(dst), "l"(src), "r"(srcsz) : "memory");
}
#define CP_COMMIT() asm volatile("cp.async.commit_group;" ::: "memory")
#define CP_WAIT0()  asm volatile("cp.async.wait_group 0;" ::: "memory")
#define CP_WAIT1()  asm volatile("cp.async.wait_group 1;" ::: "memory")

__device__ __forceinline__ u32 swz(u32 o) { return o ^ ((o >> 3) & 0x70); }
__device__ __forceinline__ void split2(float v, bf16& h, bf16& l) {
    h = __float2bfloat16(v);
    l = __float2bfloat16(v - __bfloat162float(h));
}
union BQ { bf16 b[4]; uint2 u; };

__device__ __forceinline__ void ld_tile_async(char* sm, u32 off, const bf16* __restrict__ src,
    long long ld, int rowBase, int rowMax, long long kBase, int rows, int tid)
{
    for (int f = tid; f < rows * 8; f += 256) {
        int r = f >> 3, ch = f & 7;
        int gr = rowBase + r;
        bool ok = (gr < rowMax);
        const bf16* g = src + (size_t)(ok ? gr : rowBase) * ld + kBase + (ok ? ch * 8 : 0);
        cpasync16(s2u(sm + off + swz((u32)(r * 128 + ch * 16))), g, ok ? 16 : 0);
    }
}
__device__ __forceinline__ void ld_tile(char* sm, u32 off, const bf16* __restrict__ src,
    long long ld, int rowBase, int rowMax, long long kBase, long long kMax, int rows, int tid)
{
    const uint4 z = make_uint4(0, 0, 0, 0);
    for (int f = tid; f < rows * 8; f += 256) {
        int r = f >> 3, ch = f & 7;
        int gr = rowBase + r;
        uint4 v = (gr < rowMax && kBase + ch * 8 < kMax)
            ? *(const uint4*)(src + (size_t)gr * ld + kBase + ch * 8) : z;
        *(uint4*)(sm + off + swz((u32)(r * 128 + ch * 16))) = v;
    }
}

// ===========================================================================
// HMMA GEMM NT: C = alpha*(Ah.Bh + Ah.Bl + Al.Bh) + bias
// 128x128 tile, K-slab 64 (K%64==0), 256 threads = 8 warps (4x2), warp 32x64.
// mode 0: fp32 C; 1: bf16 split out; 2: transposed split.
// statsFlag: emit per-row softmax partials (max, sumexp) into pmax/psum
// indexed [(gm*NH + blockIdx.z)*NT + blockIdx.y].
// ===========================================================================
__global__ __launch_bounds__(256, 1) void hm_gemm(
    const bf16* __restrict__ Ah, const bf16* __restrict__ Al,
    const bf16* __restrict__ Bh, const bf16* __restrict__ Bl,
    float* __restrict__ C, bf16* __restrict__ outH, bf16* __restrict__ outL,
    const float* __restrict__ bias, float* __restrict__ pmax, float* __restrict__ psum,
    int M, int N, int K, int lda, int ldb, long long ldc, long long ldo,
    int zk, long long cZs, float alpha, int mode, int statsFlag)
{
    extern __shared__ char sm[];
    const int tid = threadIdx.x, lane = tid & 31, w = tid >> 5;
    const int wm = w >> 1, wn = w & 1;
    const int mBase = blockIdx.x * 128, nBase = blockIdx.y * 128;
    const long long kOff = (long long)zk * blockIdx.z;
    C += (size_t)blockIdx.z * cZs;

    float acc[2][8][4];
    #pragma unroll
    for (int t = 0; t < 2; t++)
        #pragma unroll
        for (int j = 0; j < 8; j++)
            #pragma unroll
            for (int q = 0; q < 4; q++) acc[t][j][q] = 0.f;

    const int ns = K / 64;
    {
        long long kB = kOff;
        ld_tile_async(sm, 1024,         Ah, lda, mBase, M, kB, 128, tid);
        ld_tile_async(sm, 1024 + 16384, Al, lda, mBase, M, kB, 128, tid);
        ld_tile_async(sm, 1024 + 32768, Bh, ldb, nBase, N, kB, 128, tid);
        ld_tile_async(sm, 1024 + 49152, Bl, ldb, nBase, N, kB, 128, tid);
        CP_COMMIT();
    }
    const u32 rsel = lane & 15, csel = (u32)((lane >> 4) << 4);
    for (int s = 0; s < ns; s++) {
        if (s + 1 < ns) {
            u32 bo2 = 1024 + ((s + 1) & 1) * 65536;
            long long kB = kOff + (long long)(s + 1) * 64;
            ld_tile_async(sm, bo2,         Ah, lda, mBase, M, kB, 128, tid);
            ld_tile_async(sm, bo2 + 16384, Al, lda, mBase, M, kB, 128, tid);
            ld_tile_async(sm, bo2 + 32768, Bh, ldb, nBase, N, kB, 128, tid);
            ld_tile_async(sm, bo2 + 49152, Bl, ldb, nBase, N, kB, 128, tid);
            CP_COMMIT();
            CP_WAIT1();
        } else {
            CP_WAIT0();
        }
        __syncthreads();
        const u32 bo = 1024 + (s & 1) * 65536;
        const u32 aH = s2u(sm + bo), aL = aH + 16384, bH = aH + 32768, bL = aH + 49152;
        #pragma unroll
        for (int kk = 0; kk < 4; kk++) {
            const u32 cb = kk * 32 + csel;
            u32 ah[2][4], al[2][4];
            #pragma unroll
            for (int t = 0; t < 2; t++) {
                u32 o = swz((u32)((wm * 32 + t * 16 + rsel) * 128) + cb);
                ldsm4(ah[t], aH + o);
                ldsm4(al[t], aL + o);
            }
            u32 bh[8][2], bl[8][2];
            #pragma unroll
            for (int u = 0; u < 4; u++) {
                u32 o = swz((u32)((wn * 64 + u * 16 + rsel) * 128) + cb);
                u32 m[4], ml[4];
                ldsm4(m, bH + o); ldsm4(ml, bL + o);
                bh[2*u][0] = m[0];  bh[2*u][1] = m[2];
                bh[2*u+1][0] = m[1]; bh[2*u+1][1] = m[3];
                bl[2*u][0] = ml[0];  bl[2*u][1] = ml[2];
                bl[2*u+1][0] = ml[1]; bl[2*u+1][1] = ml[3];
            }
            #pragma unroll
            for (int t = 0; t < 2; t++)
                #pragma unroll
                for (int j = 0; j < 8; j++) {
                    mma16816(acc[t][j], ah[t], bh[j]);
                    mma16816(acc[t][j], ah[t], bl[j]);
                    mma16816(acc[t][j], al[t], bh[j]);
                }
        }
        __syncthreads();
    }

    float* stg = (float*)(sm + 1024);
    #pragma unroll
    for (int t = 0; t < 2; t++)
        #pragma unroll
        for (int j = 0; j < 8; j++) {
            int r0 = wm * 32 + t * 16 + (lane >> 2);
            int c0 = wn * 64 + j * 8 + 2 * (lane & 3);
            float b0 = 0.f, b1 = 0.f;
            if (bias) {
                if (nBase + c0 < N)     b0 = bias[nBase + c0];
                if (nBase + c0 + 1 < N) b1 = bias[nBase + c0 + 1];
            }
            stg[r0 * 128 + c0]           = acc[t][j][0] * alpha + b0;
            stg[r0 * 128 + c0 + 1]       = acc[t][j][1] * alpha + b1;
            stg[(r0 + 8) * 128 + c0]     = acc[t][j][2] * alpha + b0;
            stg[(r0 + 8) * 128 + c0 + 1] = acc[t][j][3] * alpha + b1;
        }
    __syncthreads();

    if (statsFlag) {
        // per-row softmax partials over the valid columns of this tile
        int r = tid >> 1, half = tid & 1;
        int nv = N - nBase; if (nv > 128) nv = 128;
        float m = -1e30f, ssum = 0.f;
        int cEnd = half * 64 + 64; if (cEnd > nv) cEnd = nv;
        for (int c = half * 64; c < cEnd; c++) {
            float x = stg[r * 128 + c];
            float mn = fmaxf(m, x);
            ssum = ssum * __expf(m - mn) + __expf(x - mn);
            m = mn;
        }
        float m2 = __shfl_xor_sync(0xffffffffu, m, 1);
        float s2 = __shfl_xor_sync(0xffffffffu, ssum, 1);
        float mn = fmaxf(m, m2);
        ssum = ssum * __expf(m - mn) + s2 * __expf(m2 - mn);
        if (half == 0) {
            size_t idx = ((size_t)(mBase + r) * NH + blockIdx.z) * NT + blockIdx.y;
            pmax[idx] = mn; psum[idx] = ssum;
        }
    }

    if (mode == 0) {
        for (int i = tid; i < 128 * 32; i += 256) {
            int r = i >> 5, c4 = (i & 31) * 4;
            int gm = mBase + r, n = nBase + c4;
            if (gm < M && n < N)
                *(float4*)(C + (size_t)gm * ldc + n) = *(float4*)(stg + r * 128 + c4);
        }
    } else if (mode == 1) {
        for (int i = tid; i < 128 * 32; i += 256) {
            int r = i >> 5, c4 = (i & 31) * 4;
            int gm = mBase + r, n = nBase + c4;
            if (gm < M && n < N) {
                float4 v = *(float4*)(stg + r * 128 + c4);
                BQ H, L;
                split2(v.x, H.b[0], L.b[0]); split2(v.y, H.b[1], L.b[1]);
                split2(v.z, H.b[2], L.b[2]); split2(v.w, H.b[3], L.b[3]);
                *(uint2*)(outH + (size_t)gm * ldo + n) = H.u;
                *(uint2*)(outL + (size_t)gm * ldo + n) = L.u;
            }
        }
    } else {
        for (int i = tid; i < 128 * 32; i += 256) {
            int c = i >> 5, g4 = (i & 31) * 4;
            int on = nBase + c, og = mBase + g4;
            if (on < N && og < M) {
                float v0 = stg[(g4 + 0) * 128 + c], v1 = stg[(g4 + 1) * 128 + c];
                float v2 = stg[(g4 + 2) * 128 + c], v3 = stg[(g4 + 3) * 128 + c];
                BQ H, L;
                split2(v0, H.b[0], L.b[0]); split2(v1, H.b[1], L.b[1]);
                split2(v2, H.b[2], L.b[2]); split2(v3, H.b[3], L.b[3]);
                *(uint2*)(outH + (size_t)on * ldo + og) = H.u;
                *(uint2*)(outL + (size_t)on * ldo + og) = L.u;
            }
        }
    }
}

// combine per-tile partials -> g_m, g_l. 8 rows per 256-thread block.
__global__ __launch_bounds__(256) void stats_reduce(
    const float* __restrict__ pmax, const float* __restrict__ psum)
{
    int row = blockIdx.x * 8 + (threadIdx.x >> 5);
    int lane = threadIdx.x & 31;
    float m = -1e30f, s = 0.f;
    for (int t = lane; t < 157; t += 32) {
        float pm = pmax[(size_t)row * NT + t], ps = psum[(size_t)row * NT + t];
        float mn = fmaxf(m, pm);
        s = s * __expf(m - mn) + ps * __expf(pm - mn);
        m = mn;
    }
    #pragma unroll
    for (int o = 16; o; o >>= 1) {
        float m2 = __shfl_xor_sync(0xffffffffu, m, o);
        float s2 = __shfl_xor_sync(0xffffffffu, s, o);
        float mn = fmaxf(m, m2);
        s = s * __expf(m - mn) + s2 * __expf(m2 - mn);
        m = mn;
    }
    if (lane == 0) { g_m[row] = m; g_l[row] = 1.f / s; }
}

// ===========================================================================
// PV HMMA + fused softmax + attn writeback.
// part[ch][b][h*64+d] = sum_g softmax(S)[b,h,g] * Vt[h*64+d][g]; also writes
// the normalized fp32 softmax values back into S (each element exactly once).
// Grid (2, NH, PVKS).
// ===========================================================================
__global__ __launch_bounds__(256, 1) void hm_pv(
    float* __restrict__ S, const bf16* __restrict__ Vth,
    const bf16* __restrict__ Vtl, float* __restrict__ part)
{
    extern __shared__ char sm[];
    const int tid = threadIdx.x, lane = tid & 31, w = tid >> 5;
    const int wm = w >> 1, wn = w & 1;
    const int mBase = blockIdx.x * 128, h = blockIdx.y, ch = blockIdx.z;
    const long long kbeg = (long long)ch * PVCH;
    const long long kend = (kbeg + PVCH < NG) ? kbeg + PVCH : NG;
    const int ns = (int)((kend - kbeg + 63) / 64);

    float acc[2][4][4];
    #pragma unroll
    for (int t = 0; t < 2; t++)
        #pragma unroll
        for (int j = 0; j < 4; j++)
            #pragma unroll
            for (int q = 0; q < 4; q++) acc[t][j][q] = 0.f;

    const u32 rsel = lane & 15, csel = (u32)((lane >> 4) << 4);
    for (int s = 0; s < ns; s++) {
        long long kB = kbeg + (long long)s * 64;
        __syncthreads();
        for (int f = tid; f < 128 * 16; f += 256) {
            int r = f >> 4, c4 = f & 15;
            int b = mBase + r;
            long long g = kB + c4 * 4;
            bool ok = g < kend;
            float* sp = S + (size_t)b * (NH * NG) + (size_t)h * NG + g;
            float4 v = ok ? *(const float4*)sp : make_float4(0.f, 0.f, 0.f, 0.f);
            float m = g_m[b * NH + h], il = g_l[b * NH + h];
            float e0 = ok ? __expf(v.x - m) * il : 0.f;
            float e1 = ok ? __expf(v.y - m) * il : 0.f;
            float e2 = ok ? __expf(v.z - m) * il : 0.f;
            float e3 = ok ? __expf(v.w - m) * il : 0.f;
            if (ok) *(float4*)sp = make_float4(e0, e1, e2, e3);   // fused norm
            BQ H, L;
            split2(e0, H.b[0], L.b[0]); split2(e1, H.b[1], L.b[1]);
            split2(e2, H.b[2], L.b[2]); split2(e3, H.b[3], L.b[3]);
            u32 o = swz((u32)(r * 128 + c4 * 8));
            *(uint2*)(sm + 1024 + o) = H.u;
            *(uint2*)(sm + 1024 + 16384 + o) = L.u;
        }
        ld_tile(sm, 1024 + 32768, Vth, NG, h * 64, NL, kB, kend, 64, tid);
        ld_tile(sm, 1024 + 40960, Vtl, NG, h * 64, NL, kB, kend, 64, tid);
        __syncthreads();
        const u32 aH = s2u(sm + 1024), aL = aH + 16384, bH = aH + 32768, bL = aH + 40960;
        #pragma unroll
        for (int kk = 0; kk < 4; kk++) {
            const u32 cb = kk * 32 + csel;
            u32 ah[2][4], al[2][4];
            #pragma unroll
            for (int t = 0; t < 2; t++) {
                u32 o = swz((u32)((wm * 32 + t * 16 + rsel) * 128) + cb);
                ldsm4(ah[t], aH + o);
                ldsm4(al[t], aL + o);
            }
            u32 bh[4][2], bl[4][2];
            #pragma unroll
            for (int u = 0; u < 2; u++) {
                u32 o = swz((u32)((wn * 32 + u * 16 + rsel) * 128) + cb);
                u32 m[4], ml[4];
                ldsm4(m, bH + o); ldsm4(ml, bL + o);
                bh[2*u][0] = m[0];  bh[2*u][1] = m[2];
                bh[2*u+1][0] = m[1]; bh[2*u+1][1] = m[3];
                bl[2*u][0] = ml[0];  bl[2*u][1] = ml[2];
                bl[2*u+1][0] = ml[1]; bl[2*u+1][1] = ml[3];
            }
            #pragma unroll
            for (int t = 0; t < 2; t++)
                #pragma unroll
                for (int j = 0; j < 4; j++) {
                    mma16816(acc[t][j], ah[t], bh[j]);
                    mma16816(acc[t][j], ah[t], bl[j]);
                    mma16816(acc[t][j], al[t], bh[j]);
                }
        }
    }
    __syncthreads();

    float* stg = (float*)(sm + 1024);
    #pragma unroll
    for (int t = 0; t < 2; t++)
        #pragma unroll
        for (int j = 0; j < 4; j++) {
            int r0 = wm * 32 + t * 16 + (lane >> 2);
            int c0 = wn * 32 + j * 8 + 2 * (lane & 3);
            stg[r0 * 64 + c0]           = acc[t][j][0];
            stg[r0 * 64 + c0 + 1]       = acc[t][j][1];
            stg[(r0 + 8) * 64 + c0]     = acc[t][j][2];
            stg[(r0 + 8) * 64 + c0 + 1] = acc[t][j][3];
        }
    __syncthreads();
    for (int i = tid; i < 128 * 16; i += 256) {
        int r = i >> 4, c4 = (i & 15) * 4;
        *(float4*)(part + ((size_t)ch * NB + mBase + r) * NL + h * 64 + c4)
            = *(float4*)(stg + r * 64 + c4);
    }
}

// -------- small kernels --------
__global__ __launch_bounds__(256) void split_kernel(
    const float* __restrict__ s, bf16* __restrict__ oh, bf16* __restrict__ ol, long long n4)
{
    long long i = (long long)blockIdx.x * 256 + threadIdx.x;
    long long st = (long long)gridDim.x * 256;
    for (; i < n4; i += st) {
        float4 v = ((const float4*)s)[i];
        BQ H, L;
        split2(v.x, H.b[0], L.b[0]); split2(v.y, H.b[1], L.b[1]);
        split2(v.z, H.b[2], L.b[2]); split2(v.w, H.b[3], L.b[3]);
        ((uint2*)oh)[i] = H.u; ((uint2*)ol)[i] = L.u;
    }
}

__global__ __launch_bounds__(256) void pv_reduce_split(
    const float* __restrict__ part, bf16* __restrict__ oh, bf16* __restrict__ ol)
{
    const int idx = blockIdx.x * 256 + threadIdx.x;
    float s = 0.f;
    #pragma unroll
    for (int c = 0; c < PVKS; c++) s += part[(size_t)c * NB * NL + idx];
    bf16 h, l; split2(s, h, l);
    oh[idx] = h; ol[idx] = l;
}

__global__ __launch_bounds__(256) void ln_relu_split(
    const float* __restrict__ hf, const float* __restrict__ g,
    const float* __restrict__ bt, bf16* __restrict__ oh, bf16* __restrict__ ol)
{
    const int b = blockIdx.x, tid = threadIdx.x;
    float x0 = hf[(size_t)b * NL + tid], x1 = hf[(size_t)b * NL + tid + 256];
    __shared__ float s1[256], s2[256];
    s1[tid] = x0 + x1; s2[tid] = x0 * x0 + x1 * x1;
    __syncthreads();
    for (int off = 128; off; off >>= 1) {
        if (tid < off) { s1[tid] += s1[tid + off]; s2[tid] += s2[tid + off]; }
        __syncthreads();
    }
    const float mu = s1[0] * (1.f / 512.f);
    const float var = s2[0] * (1.f / 512.f) - mu * mu;
    const float rs = rsqrtf(var + 1e-5f);
    float y0 = fmaxf((x0 - mu) * rs * g[tid] + bt[tid], 0.f);
    float y1 = fmaxf((x1 - mu) * rs * g[tid + 256] + bt[tid + 256], 0.f);
    bf16 h, l;
    split2(y0, h, l); oh[(size_t)b * NL + tid] = h;       ol[(size_t)b * NL + tid] = l;
    split2(y1, h, l); oh[(size_t)b * NL + tid + 256] = h; ol[(size_t)b * NL + tid + 256] = l;
}

// ---------------------------------------------------------------------------
extern "C" void kernel_launch(void* const* d_in, const int* in_sizes, int n_in,
                              void* d_out, int out_size)
{
    const float* z   = (const float*)d_in[0];
    const float* E   = (const float*)d_in[1];
    const float* Wq  = (const float*)d_in[2];
    const float* bq  = (const float*)d_in[3];
    const float* Wk  = (const float*)d_in[4];
    const float* bk  = (const float*)d_in[5];
    const float* Wv  = (const float*)d_in[6];
    const float* bv  = (const float*)d_in[7];
    const float* W1  = (const float*)d_in[8];
    const float* b1  = (const float*)d_in[9];
    const float* lng = (const float*)d_in[10];
    const float* lnb = (const float*)d_in[11];
    const float* W2  = (const float*)d_in[12];
    const float* b2  = (const float*)d_in[13];

    float* out  = (float*)d_out;
    float* ga   = out;
    float* attn = out + (size_t)NB * NG;   // raw scores -> normalized in PV

    cudaFuncSetAttribute(hm_gemm, cudaFuncAttributeMaxDynamicSharedMemorySize, GEMM_SMEM);
    cudaFuncSetAttribute(hm_pv,   cudaFuncAttributeMaxDynamicSharedMemorySize, PV_SMEM);

    bf16 *Eh, *El, *W2h, *W2l, *Kh, *Kl, *Vth, *Vtl, *Wqh, *Wql, *Wkh, *Wkl,
         *Wvh, *Wvl, *W1h, *W1l, *zh, *zl, *Qh, *Ql, *ch, *cl, *h1h, *h1l;
    float *h1f, *part, *pmax, *psum;
    cudaGetSymbolAddress((void**)&Eh, g_Eh);   cudaGetSymbolAddress((void**)&El, g_El);
    cudaGetSymbolAddress((void**)&W2h, g_W2h); cudaGetSymbolAddress((void**)&W2l, g_W2l);
    cudaGetSymbolAddress((void**)&Kh, g_Kh);   cudaGetSymbolAddress((void**)&Kl, g_Kl);
    cudaGetSymbolAddress((void**)&Vth, g_Vth); cudaGetSymbolAddress((void**)&Vtl, g_Vtl);
    cudaGetSymbolAddress((void**)&Wqh, g_Wqh); cudaGetSymbolAddress((void**)&Wql, g_Wql);
    cudaGetSymbolAddress((void**)&Wkh, g_Wkh); cudaGetSymbolAddress((void**)&Wkl, g_Wkl);
    cudaGetSymbolAddress((void**)&Wvh, g_Wvh); cudaGetSymbolAddress((void**)&Wvl, g_Wvl);
    cudaGetSymbolAddress((void**)&W1h, g_W1h); cudaGetSymbolAddress((void**)&W1l, g_W1l);
    cudaGetSymbolAddress((void**)&zh, g_zh);   cudaGetSymbolAddress((void**)&zl, g_zl);
    cudaGetSymbolAddress((void**)&Qh, g_Qh);   cudaGetSymbolAddress((void**)&Ql, g_Ql);
    cudaGetSymbolAddress((void**)&ch, g_ch);   cudaGetSymbolAddress((void**)&cl, g_cl);
    cudaGetSymbolAddress((void**)&h1h, g_h1h); cudaGetSymbolAddress((void**)&h1l, g_h1l);
    cudaGetSymbolAddress((void**)&h1f, g_h1f); cudaGetSymbolAddress((void**)&part, g_part);
    cudaGetSymbolAddress((void**)&pmax, g_pmax); cudaGetSymbolAddress((void**)&psum, g_psum);

    const int gT = (NG + 127) / 128;   // 157

    split_kernel<<<1024, 256>>>(E,  Eh,  El,  (long long)NG * ND / 4);
    split_kernel<<<1024, 256>>>(W2, W2h, W2l, (long long)NG * NL / 4);
    split_kernel<<<256, 256>>>(Wq, Wqh, Wql, NL * NL / 4);
    split_kernel<<<128, 256>>>(Wk, Wkh, Wkl, NL * ND / 4);
    split_kernel<<<128, 256>>>(Wv, Wvh, Wvl, NL * ND / 4);
    split_kernel<<<256, 256>>>(W1, W1h, W1l, NL * NL / 4);
    split_kernel<<<128, 256>>>(z,  zh,  zl,  NB * NL / 4);

    // K = E@Wk^T + bk -> bf16 split [NG, NL]
    hm_gemm<<<dim3(gT, 4, 1), 256, GEMM_SMEM>>>(Eh, El, Wkh, Wkl, nullptr, Kh, Kl, bk,
        nullptr, nullptr, NG, NL, ND, ND, ND, 0, NL, 0, 0, 1.f, 1, 0);
    // Vt = (E@Wv^T + bv)^T -> bf16 split [NL, NG]
    hm_gemm<<<dim3(gT, 4, 1), 256, GEMM_SMEM>>>(Eh, El, Wvh, Wvl, nullptr, Vth, Vtl, bv,
        nullptr, nullptr, NG, NL, ND, ND, ND, 0, NG, 0, 0, 1.f, 2, 0);
    // Q = z@Wq^T + bq -> bf16 split [NB, NL]
    hm_gemm<<<dim3(2, 4, 1), 256, GEMM_SMEM>>>(zh, zl, Wqh, Wql, nullptr, Qh, Ql, bq,
        nullptr, nullptr, NB, NL, NL, NL, NL, 0, NL, 0, 0, 1.f, 1, 0);
    // raw scores -> attn region, with fused per-tile softmax partials
    hm_gemm<<<dim3(2, gT, NH), 256, SCORES_SMEM>>>(Qh, Ql, Kh, Kl, attn, nullptr, nullptr,
        nullptr, pmax, psum, NB, NG, 64, NL, NL, (long long)NH * NG, 0, 64,
        (long long)NG, ATT_SCALE, 0, 1);
    // combine partials -> g_m, g_l
    stats_reduce<<<NB * NH / 8, 256>>>(pmax, psum);
    // PV: fused exp + attn writeback + GEMM
    hm_pv<<<dim3(2, NH, PVKS), 256, PV_SMEM>>>(attn, Vth, Vtl, part);
    pv_reduce_split<<<(NB * NL) / 256, 256>>>(part, ch, cl);
    // h1 = ctx@W1^T + b1 (fp32), LN+ReLU -> bf16 split
    hm_gemm<<<dim3(2, 4, 1), 256, GEMM_SMEM>>>(ch, cl, W1h, W1l, h1f, nullptr, nullptr, b1,
        nullptr, nullptr, NB, NL, NL, NL, NL, NL, 0, 0, 0, 1.f, 0, 0);
    ln_relu_split<<<NB, 256>>>(h1f, lng, lnb, h1h, h1l);
    // gene_attention = h1@W2^T + b2
    hm_gemm<<<dim3(2, gT, 1), 256, GEMM_SMEM>>>(h1h, h1l, W2h, W2l, ga, nullptr, nullptr, b2,
        nullptr, nullptr, NB, NG, NL, NL, NL, (long long)NG, 0, 0, 0, 1.f, 0, 0);
}